// round 4
// baseline (speedup 1.0000x reference)
#include <cuda_runtime.h>
#include <cuda_bf16.h>

// Problem constants
#define BB   2
#define SS   2048
#define DD   1024
#define HH   16
#define DHH  64
#define WIN  256
#define MM   (BB * SS)        // 4096 rows for all GEMMs

// ---------------------------------------------------------------------------
// Scratch (no cudaMalloc allowed): q/k/v in [B,H,S,DH] layout, attn out in
// [B,S,D] layout (head-major within D, matching the reference reshape).
// ---------------------------------------------------------------------------
__device__ float g_q[MM * DD];
__device__ float g_k[MM * DD];
__device__ float g_v[MM * DD];
__device__ float g_attn[MM * DD];

// ---------------------------------------------------------------------------
// SGEMM core: C[M,N] = A[M,K] @ W[N,K]^T + bias, M=4096, N=1024, K=1024.
// 128x128 block tile, BK=16, 256 threads, 8x8 per thread (2x2 groups of 4x4).
// Global->reg prefetch overlaps compute. HEAD=true scatters the output into
// the [B,H,S,DH] head-split layout.
// ---------------------------------------------------------------------------
template <bool HEAD>
__device__ __forceinline__ void gemm_core(const float* __restrict__ A,
                                          const float* __restrict__ W,
                                          const float* __restrict__ bias,
                                          float* __restrict__ C)
{
    constexpr int K = DD;
    __shared__ float As[16][128];
    __shared__ float Bs[16][128];

    const int tid = threadIdx.x;
    const int tx  = tid & 15;
    const int ty  = tid >> 4;
    const int m0  = blockIdx.y * 128;
    const int n0  = blockIdx.x * 128;

    // global-load indexing: each thread loads 2 float4 from A and 2 from W
    const int r0a = tid >> 2;          // 0..63
    const int c0a = (tid & 3) * 4;     // 0,4,8,12

    const float* Abase = A + m0 * K;
    const float* Wbase = W + n0 * K;

    float4 pa[2], pw[2];
#pragma unroll
    for (int p = 0; p < 2; ++p) {
        pa[p] = *(const float4*)(Abase + (r0a + 64 * p) * K + c0a);
        pw[p] = *(const float4*)(Wbase + (r0a + 64 * p) * K + c0a);
    }

    float acc[8][8];
#pragma unroll
    for (int i = 0; i < 8; ++i)
#pragma unroll
        for (int j = 0; j < 8; ++j) acc[i][j] = 0.0f;

    const int NT = K / 16;
    for (int kt = 0; kt < NT; ++kt) {
        __syncthreads();   // previous tile fully consumed
#pragma unroll
        for (int p = 0; p < 2; ++p) {
            const int r = r0a + 64 * p;
            As[c0a + 0][r] = pa[p].x; As[c0a + 1][r] = pa[p].y;
            As[c0a + 2][r] = pa[p].z; As[c0a + 3][r] = pa[p].w;
            Bs[c0a + 0][r] = pw[p].x; Bs[c0a + 1][r] = pw[p].y;
            Bs[c0a + 2][r] = pw[p].z; Bs[c0a + 3][r] = pw[p].w;
        }
        __syncthreads();

        if (kt + 1 < NT) {
            const int k0 = (kt + 1) * 16;
#pragma unroll
            for (int p = 0; p < 2; ++p) {
                pa[p] = *(const float4*)(Abase + (r0a + 64 * p) * K + k0 + c0a);
                pw[p] = *(const float4*)(Wbase + (r0a + 64 * p) * K + k0 + c0a);
            }
        }

#pragma unroll
        for (int kk = 0; kk < 16; ++kk) {
            float a[8], b[8];
            *(float4*)&a[0] = *(const float4*)&As[kk][ty * 4];
            *(float4*)&a[4] = *(const float4*)&As[kk][64 + ty * 4];
            *(float4*)&b[0] = *(const float4*)&Bs[kk][tx * 4];
            *(float4*)&b[4] = *(const float4*)&Bs[kk][64 + tx * 4];
#pragma unroll
            for (int i = 0; i < 8; ++i)
#pragma unroll
                for (int j = 0; j < 8; ++j)
                    acc[i][j] += a[i] * b[j];
        }
    }

    // epilogue: bias + store (plain or head-split)
#pragma unroll
    for (int cg = 0; cg < 2; ++cg) {
        const int nb = n0 + cg * 64 + tx * 4;
        const float4 bv4 = *(const float4*)(bias + nb);
#pragma unroll
        for (int rg = 0; rg < 2; ++rg) {
#pragma unroll
            for (int i = 0; i < 4; ++i) {
                const int m = m0 + rg * 64 + ty * 4 + i;
                float4 o;
                o.x = acc[rg * 4 + i][cg * 4 + 0] + bv4.x;
                o.y = acc[rg * 4 + i][cg * 4 + 1] + bv4.y;
                o.z = acc[rg * 4 + i][cg * 4 + 2] + bv4.z;
                o.w = acc[rg * 4 + i][cg * 4 + 3] + bv4.w;
                if (HEAD) {
                    const int bb = m >> 11;       // m / 2048
                    const int s  = m & 2047;
                    const int h  = nb >> 6;       // nb is multiple of 4, h-block aligned
                    const int dh = nb & 63;
                    *(float4*)(C + (((bb * HH + h) * SS + s) * DHH + dh)) = o;
                } else {
                    *(float4*)(C + m * DD + nb) = o;
                }
            }
        }
    }
}

// QKV projections fused across grid.z (better wave packing: 768 CTAs).
__global__ __launch_bounds__(256)
void gemm_qkv(const float* __restrict__ q, const float* __restrict__ k,
              const float* __restrict__ v,
              const float* __restrict__ Wq, const float* __restrict__ bq,
              const float* __restrict__ Wk, const float* __restrict__ bk,
              const float* __restrict__ Wv, const float* __restrict__ bv)
{
    const float* A; const float* W; const float* bias; float* C;
    if (blockIdx.z == 0)      { A = q; W = Wq; bias = bq; C = g_q; }
    else if (blockIdx.z == 1) { A = k; W = Wk; bias = bk; C = g_k; }
    else                      { A = v; W = Wv; bias = bv; C = g_v; }
    gemm_core<true>(A, W, bias, C);
}

__global__ __launch_bounds__(256)
void gemm_out(const float* __restrict__ Wo, const float* __restrict__ bo,
              float* __restrict__ out)
{
    gemm_core<false>(g_attn, Wo, bo, out);
}

// ---------------------------------------------------------------------------
// Windowed causal flash attention.
// Grid: (S/64, H, B). Block: 256 threads (16x16).
// Thread (ty,tx): scores S[ty*4+i][tx*4+j], output O[ty*4+i][tx*4+dd].
// Per (b,h,qblock): iterate key tiles kt in [qb-4 .. qb] (clamped to 0).
// Online softmax stats per row, replicated across the 16 tx lanes via shfl.
// ---------------------------------------------------------------------------
#define SMEM_FLOATS (3 * 64 * 65 + 64 * 64)
#define SMEM_BYTES  (SMEM_FLOATS * 4)

__global__ __launch_bounds__(256)
void attn_kernel()
{
    extern __shared__ float sm[];
    float* Qs = sm;                 // [64][65]
    float* Ks = Qs + 64 * 65;       // [64][65]
    float* Sb = Ks + 64 * 65;       // [64][65]  scores -> probs
    float* Vs = Sb + 64 * 65;       // [64][64]

    const int tid = threadIdx.x;
    const int tx  = tid & 15;
    const int ty  = tid >> 4;
    const int qb  = blockIdx.x;
    const int h   = blockIdx.y;
    const int b   = blockIdx.z;
    const int q0  = qb * 64;
    const float scale = 0.125f;     // DH^-0.5 = 1/8

    const float* Qg = g_q + (b * HH + h) * SS * DHH;
    const float* Kg = g_k + (b * HH + h) * SS * DHH;
    const float* Vg = g_v + (b * HH + h) * SS * DHH;

    // Q tile
#pragma unroll
    for (int p = 0; p < 4; ++p) {
        const int idx = tid + 256 * p;
        const int r = idx >> 4, c = (idx & 15) * 4;
        const float4 v4 = *(const float4*)(Qg + (q0 + r) * DHH + c);
        Qs[r * 65 + c + 0] = v4.x; Qs[r * 65 + c + 1] = v4.y;
        Qs[r * 65 + c + 2] = v4.z; Qs[r * 65 + c + 3] = v4.w;
    }

    float acc[4][4];
    float mrow[4], lrow[4];
#pragma unroll
    for (int i = 0; i < 4; ++i) {
        mrow[i] = -1e30f; lrow[i] = 0.0f;
#pragma unroll
        for (int j = 0; j < 4; ++j) acc[i][j] = 0.0f;
    }

    int kt_lo = qb - 4; if (kt_lo < 0) kt_lo = 0;
    for (int kt = kt_lo; kt <= qb; ++kt) {
        const int k0 = kt * 64;
        __syncthreads();            // Ks/Vs/Sb free to overwrite
#pragma unroll
        for (int p = 0; p < 4; ++p) {
            const int idx = tid + 256 * p;
            const int r = idx >> 4, c = (idx & 15) * 4;
            const float4 kv = *(const float4*)(Kg + (k0 + r) * DHH + c);
            Ks[r * 65 + c + 0] = kv.x; Ks[r * 65 + c + 1] = kv.y;
            Ks[r * 65 + c + 2] = kv.z; Ks[r * 65 + c + 3] = kv.w;
            *(float4*)(Vs + r * 64 + c) = *(const float4*)(Vg + (k0 + r) * DHH + c);
        }
        __syncthreads();

        // ---- scores: 4x4 register block, dot over DH=64 ----
        float s[4][4];
#pragma unroll
        for (int i = 0; i < 4; ++i)
#pragma unroll
            for (int j = 0; j < 4; ++j) s[i][j] = 0.0f;

        const float* qrow = Qs + (ty * 4) * 65;
        const float* krow = Ks + (tx * 4) * 65;
#pragma unroll 8
        for (int d = 0; d < 64; ++d) {
            float qv[4], kv[4];
#pragma unroll
            for (int i = 0; i < 4; ++i) qv[i] = qrow[i * 65 + d];
#pragma unroll
            for (int j = 0; j < 4; ++j) kv[j] = krow[j * 65 + d];
#pragma unroll
            for (int i = 0; i < 4; ++i)
#pragma unroll
                for (int j = 0; j < 4; ++j)
                    s[i][j] += qv[i] * kv[j];
        }

        // ---- mask + scale + tile row-max ----
        float tmax[4];
#pragma unroll
        for (int i = 0; i < 4; ++i) {
            tmax[i] = -1e30f;
            const int qi = q0 + ty * 4 + i;
#pragma unroll
            for (int j = 0; j < 4; ++j) {
                const int kj = k0 + tx * 4 + j;
                const bool valid = (kj <= qi) && (kj > qi - WIN);
                s[i][j] = valid ? s[i][j] * scale : -1e30f;
                tmax[i] = fmaxf(tmax[i], s[i][j]);
            }
        }
#pragma unroll
        for (int i = 0; i < 4; ++i)
#pragma unroll
            for (int off = 1; off < 16; off <<= 1)
                tmax[i] = fmaxf(tmax[i], __shfl_xor_sync(0xffffffffu, tmax[i], off));

        // ---- online softmax update ----
        float tsum[4], corr[4];
#pragma unroll
        for (int i = 0; i < 4; ++i) {
            const float mn = fmaxf(mrow[i], tmax[i]);
            corr[i] = __expf(mrow[i] - mn);
            mrow[i] = mn;
            tsum[i] = 0.0f;
#pragma unroll
            for (int j = 0; j < 4; ++j) {
                // guard: fully-masked entries must contribute exactly 0
                const float p = (s[i][j] > -1e29f) ? __expf(s[i][j] - mn) : 0.0f;
                Sb[(ty * 4 + i) * 65 + tx * 4 + j] = p;
                tsum[i] += p;
            }
        }
#pragma unroll
        for (int i = 0; i < 4; ++i)
#pragma unroll
            for (int off = 1; off < 16; off <<= 1)
                tsum[i] += __shfl_xor_sync(0xffffffffu, tsum[i], off);
#pragma unroll
        for (int i = 0; i < 4; ++i) {
            lrow[i] = lrow[i] * corr[i] + tsum[i];
#pragma unroll
            for (int j = 0; j < 4; ++j) acc[i][j] *= corr[i];
        }
        __syncthreads();            // Sb populated by all threads

        // ---- PV: 4x4 register block over 64 keys ----
#pragma unroll 8
        for (int j = 0; j < 64; ++j) {
            float pv[4], vv[4];
#pragma unroll
            for (int i = 0; i < 4; ++i) pv[i] = Sb[(ty * 4 + i) * 65 + j];
#pragma unroll
            for (int dd = 0; dd < 4; ++dd) vv[dd] = Vs[j * 64 + tx * 4 + dd];
#pragma unroll
            for (int i = 0; i < 4; ++i)
#pragma unroll
                for (int dd = 0; dd < 4; ++dd)
                    acc[i][dd] += pv[i] * vv[dd];
        }
    }

    // ---- write output in [B,S,D] with col = h*64 + d ----
#pragma unroll
    for (int i = 0; i < 4; ++i) {
        const int qi  = q0 + ty * 4 + i;
        const float inv = 1.0f / lrow[i];
        float4 o;
        o.x = acc[i][0] * inv; o.y = acc[i][1] * inv;
        o.z = acc[i][2] * inv; o.w = acc[i][3] * inv;
        *(float4*)(g_attn + (b * SS + qi) * DD + h * DHH + tx * 4) = o;
    }
}

// ---------------------------------------------------------------------------
// Launch
// ---------------------------------------------------------------------------
extern "C" void kernel_launch(void* const* d_in, const int* in_sizes, int n_in,
                              void* d_out, int out_size)
{
    const float* query = (const float*)d_in[0];
    const float* key   = (const float*)d_in[1];
    const float* value = (const float*)d_in[2];
    const float* Wq    = (const float*)d_in[3];
    const float* bq    = (const float*)d_in[4];
    const float* Wk    = (const float*)d_in[5];
    const float* bk    = (const float*)d_in[6];
    const float* Wv    = (const float*)d_in[7];
    const float* bv    = (const float*)d_in[8];
    const float* Wo    = (const float*)d_in[9];
    const float* bo    = (const float*)d_in[10];
    float* out = (float*)d_out;

    // not a stream op: executes immediately, capture-safe, idempotent
    cudaFuncSetAttribute(attn_kernel,
                         cudaFuncAttributeMaxDynamicSharedMemorySize, SMEM_BYTES);

    dim3 blk(256);
    gemm_qkv<<<dim3(DD / 128, MM / 128, 3), blk>>>(query, key, value,
                                                   Wq, bq, Wk, bk, Wv, bv);
    attn_kernel<<<dim3(SS / 64, HH, BB), blk, SMEM_BYTES>>>();
    gemm_out<<<dim3(DD / 128, MM / 128, 1), blk>>>(Wo, bo, out);
}

// round 7
// speedup vs baseline: 1.6331x; 1.6331x over previous
#include <cuda_runtime.h>
#include <cuda_bf16.h>
#include <cstdint>

// Problem constants
#define BB   2
#define SS   2048
#define DD   1024
#define HH   16
#define DHH  64
#define WIN  256
#define MM   (BB * SS)        // 4096 rows for all GEMMs

// ---------------------------------------------------------------------------
// Scratch (no cudaMalloc allowed)
// ---------------------------------------------------------------------------
__device__ float g_q[MM * DD];        // [B,H,S,DH] head-split
__device__ float g_k[MM * DD];
__device__ float g_v[MM * DD];
__device__ float g_attn[MM * DD];     // [B,S,D]

// bf16 hi/lo split operands
__device__ __align__(16) __nv_bfloat16 g_xh[3][MM * DD];   // q,k,v inputs
__device__ __align__(16) __nv_bfloat16 g_xl[3][MM * DD];
__device__ __align__(16) __nv_bfloat16 g_wh[4][DD * DD];   // Wq,Wk,Wv,Wo
__device__ __align__(16) __nv_bfloat16 g_wl[4][DD * DD];
__device__ __align__(16) __nv_bfloat16 g_oh[MM * DD];      // attn out
__device__ __align__(16) __nv_bfloat16 g_ol[MM * DD];

// ---------------------------------------------------------------------------
// PTX helpers (sm_80-era: ldmatrix + mma.sync — valid on plain sm_103 target)
// ---------------------------------------------------------------------------
__device__ __forceinline__ uint32_t smem_u32(const void* p) {
    uint32_t a;
    asm("{ .reg .u64 t; cvta.to.shared.u64 t, %1; cvt.u32.u64 %0, t; }"
        : "=r"(a) : "l"(p));
    return a;
}

__device__ __forceinline__ void ldsm4(uint32_t& r0, uint32_t& r1,
                                      uint32_t& r2, uint32_t& r3, uint32_t addr) {
    asm volatile("ldmatrix.sync.aligned.m8n8.x4.shared.b16 {%0,%1,%2,%3}, [%4];"
                 : "=r"(r0), "=r"(r1), "=r"(r2), "=r"(r3) : "r"(addr));
}

__device__ __forceinline__ void mma16816(float* c, const uint32_t* a,
                                         uint32_t b0, uint32_t b1) {
    asm volatile(
        "mma.sync.aligned.m16n8k16.row.col.f32.bf16.bf16.f32 "
        "{%0,%1,%2,%3}, {%4,%5,%6,%7}, {%8,%9}, {%0,%1,%2,%3};"
        : "+f"(c[0]), "+f"(c[1]), "+f"(c[2]), "+f"(c[3])
        : "r"(a[0]), "r"(a[1]), "r"(a[2]), "r"(a[3]), "r"(b0), "r"(b1));
}

// ---------------------------------------------------------------------------
// hi/lo bf16 split conversion kernels
// ---------------------------------------------------------------------------
__device__ __forceinline__ void split4(float4 x, uint2& h, uint2& l) {
    __nv_bfloat16 h0 = __float2bfloat16(x.x), h1 = __float2bfloat16(x.y);
    __nv_bfloat16 h2 = __float2bfloat16(x.z), h3 = __float2bfloat16(x.w);
    __nv_bfloat16 l0 = __float2bfloat16(x.x - __bfloat162float(h0));
    __nv_bfloat16 l1 = __float2bfloat16(x.y - __bfloat162float(h1));
    __nv_bfloat16 l2 = __float2bfloat16(x.z - __bfloat162float(h2));
    __nv_bfloat16 l3 = __float2bfloat16(x.w - __bfloat162float(h3));
    h.x = (uint32_t)__bfloat16_as_ushort(h0) | ((uint32_t)__bfloat16_as_ushort(h1) << 16);
    h.y = (uint32_t)__bfloat16_as_ushort(h2) | ((uint32_t)__bfloat16_as_ushort(h3) << 16);
    l.x = (uint32_t)__bfloat16_as_ushort(l0) | ((uint32_t)__bfloat16_as_ushort(l1) << 16);
    l.y = (uint32_t)__bfloat16_as_ushort(l2) | ((uint32_t)__bfloat16_as_ushort(l3) << 16);
}

__global__ __launch_bounds__(256)
void conv_in(const float* __restrict__ q, const float* __restrict__ k,
             const float* __restrict__ v) {
    const int z = blockIdx.z;
    const float* src = (z == 0) ? q : (z == 1) ? k : v;
    __nv_bfloat16* hi = g_xh[z];
    __nv_bfloat16* lo = g_xl[z];
    const int i = (blockIdx.x * 256 + threadIdx.x) * 4;
    float4 x = *(const float4*)(src + i);
    uint2 h, l;
    split4(x, h, l);
    *(uint2*)(hi + i) = h;
    *(uint2*)(lo + i) = l;
}

__global__ __launch_bounds__(256)
void conv_w(const float* __restrict__ wq, const float* __restrict__ wk,
            const float* __restrict__ wv, const float* __restrict__ wo) {
    const int z = blockIdx.z;
    const float* src = (z == 0) ? wq : (z == 1) ? wk : (z == 2) ? wv : wo;
    __nv_bfloat16* hi = g_wh[z];
    __nv_bfloat16* lo = g_wl[z];
    const int i = (blockIdx.x * 256 + threadIdx.x) * 4;
    float4 x = *(const float4*)(src + i);
    uint2 h, l;
    split4(x, h, l);
    *(uint2*)(hi + i) = h;
    *(uint2*)(lo + i) = l;
}

__global__ __launch_bounds__(256)
void conv_o() {
    const int i = (blockIdx.x * 256 + threadIdx.x) * 4;
    float4 x = *(const float4*)(g_attn + i);
    uint2 h, l;
    split4(x, h, l);
    *(uint2*)(g_oh + i) = h;
    *(uint2*)(g_ol + i) = l;
}

// ---------------------------------------------------------------------------
// mma.sync GEMM: C[M=4096, N=1024] = A[M,K=1024] @ W[N,K]^T + bias
// fp32 accuracy via hi/lo bf16 split: ah*bh + ah*bl + al*bh.
// CTA 128x128, 8 warps (4 m x 2 n), warp tile 32x64, K chunk 32.
// smem rows padded to 80B -> conflict-free ldmatrix.
// ---------------------------------------------------------------------------
#define ROWB 80    // padded smem row stride in bytes (32 bf16 data + 8 pad)

template <bool HEAD>
__device__ __forceinline__ void gemm_mma_core(
    const __nv_bfloat16* __restrict__ Ah, const __nv_bfloat16* __restrict__ Al,
    const __nv_bfloat16* __restrict__ Bh, const __nv_bfloat16* __restrict__ Bl,
    const float* __restrict__ bias, float* __restrict__ C)
{
    __shared__ __align__(16) uint8_t smem[4][128 * ROWB];   // Ah, Al, Bh, Bl

    const int tid  = threadIdx.x;
    const int lane = tid & 31;
    const int wid  = tid >> 5;
    const int wm   = wid & 3;        // 4 warps along M (32 rows each)
    const int wn   = wid >> 2;       // 2 warps along N (64 cols each)
    const int m0   = blockIdx.y * 128;
    const int n0   = blockIdx.x * 128;

    const uint8_t* gb[4] = {
        (const uint8_t*)(Ah + m0 * DD), (const uint8_t*)(Al + m0 * DD),
        (const uint8_t*)(Bh + n0 * DD), (const uint8_t*)(Bl + n0 * DD) };

    uint32_t sb[4];
#pragma unroll
    for (int t = 0; t < 4; ++t) sb[t] = smem_u32(&smem[t][0]);

    // per-thread global-load coords (2 uint4 per tile)
    // idx = tid + 256*it : r = idx>>2 (row 0..127), g = idx&3 (16B group 0..3)
    uint4 pv[4][2];
#pragma unroll
    for (int t = 0; t < 4; ++t)
#pragma unroll
        for (int it = 0; it < 2; ++it) {
            const int idx = tid + 256 * it;
            const int rr = idx >> 2, gg = idx & 3;
            pv[t][it] = *(const uint4*)(gb[t] + rr * 2048 + gg * 16);
        }

    float acc[2][8][4];
#pragma unroll
    for (int mi = 0; mi < 2; ++mi)
#pragma unroll
        for (int nj = 0; nj < 8; ++nj)
#pragma unroll
            for (int e = 0; e < 4; ++e) acc[mi][nj][e] = 0.0f;

    for (int kc = 0; kc < 32; ++kc) {
        __syncthreads();             // previous chunk fully consumed
#pragma unroll
        for (int t = 0; t < 4; ++t)
#pragma unroll
            for (int it = 0; it < 2; ++it) {
                const int idx = tid + 256 * it;
                const int rr = idx >> 2, gg = idx & 3;
                *(uint4*)(&smem[t][rr * ROWB + gg * 16]) = pv[t][it];
            }
        __syncthreads();

        if (kc < 31) {
            const int off = (kc + 1) * 64;   // 32 bf16 = 64 bytes per chunk
#pragma unroll
            for (int t = 0; t < 4; ++t)
#pragma unroll
                for (int it = 0; it < 2; ++it) {
                    const int idx = tid + 256 * it;
                    const int rr = idx >> 2, gg = idx & 3;
                    pv[t][it] = *(const uint4*)(gb[t] + rr * 2048 + off + gg * 16);
                }
        }

#pragma unroll
        for (int ks = 0; ks < 2; ++ks) {
            const uint32_t colb  = (uint32_t)(ks * 32 + (lane >> 4) * 16);
            const int      rsel  = lane & 15;

            uint32_t ah[2][4], al[2][4];
#pragma unroll
            for (int mi = 0; mi < 2; ++mi) {
                const uint32_t roff = (uint32_t)(wm * 32 + mi * 16 + rsel) * ROWB + colb;
                ldsm4(ah[mi][0], ah[mi][1], ah[mi][2], ah[mi][3], sb[0] + roff);
                ldsm4(al[mi][0], al[mi][1], al[mi][2], al[mi][3], sb[1] + roff);
            }
            uint32_t bh[4][4], bl[4][4];
#pragma unroll
            for (int nb = 0; nb < 4; ++nb) {
                const uint32_t roff = (uint32_t)(wn * 64 + nb * 16 + rsel) * ROWB + colb;
                ldsm4(bh[nb][0], bh[nb][1], bh[nb][2], bh[nb][3], sb[2] + roff);
                ldsm4(bl[nb][0], bl[nb][1], bl[nb][2], bl[nb][3], sb[3] + roff);
            }
            // x4 on [n][k] rows: r0=(n0-7,k0-7) r1=(n8-15,k0-7) r2=(n0-7,k8-15) r3=(n8-15,k8-15)
            // b-frag for n-half hf: {r[hf], r[2+hf]}
#pragma unroll
            for (int mi = 0; mi < 2; ++mi)
#pragma unroll
                for (int nb = 0; nb < 4; ++nb)
#pragma unroll
                    for (int hf = 0; hf < 2; ++hf) {
                        float* c = acc[mi][nb * 2 + hf];
                        mma16816(c, ah[mi], bh[nb][hf], bh[nb][2 + hf]);
                        mma16816(c, ah[mi], bl[nb][hf], bl[nb][2 + hf]);
                        mma16816(c, al[mi], bh[nb][hf], bh[nb][2 + hf]);
                    }
        }
    }

    // epilogue: c0,c1 at (row=lane>>2, col=2*(lane&3)+{0,1}); c2,c3 at row+8
#pragma unroll
    for (int mi = 0; mi < 2; ++mi)
#pragma unroll
        for (int nj = 0; nj < 8; ++nj) {
            const int n  = n0 + wn * 64 + nj * 8 + 2 * (lane & 3);
            const float b0 = bias[n], b1 = bias[n + 1];
#pragma unroll
            for (int p = 0; p < 2; ++p) {
                const int m = m0 + wm * 32 + mi * 16 + (lane >> 2) + 8 * p;
                float2 o;
                o.x = acc[mi][nj][2 * p + 0] + b0;
                o.y = acc[mi][nj][2 * p + 1] + b1;
                if (HEAD) {
                    const int bb = m >> 11;
                    const int s  = m & 2047;
                    const int h  = n >> 6;
                    const int dh = n & 63;
                    *(float2*)(C + (((bb * HH + h) * SS + s) * DHH + dh)) = o;
                } else {
                    *(float2*)(C + m * DD + n) = o;
                }
            }
        }
}

__global__ __launch_bounds__(256)
void gemm_qkv_mma(const float* __restrict__ bq, const float* __restrict__ bk,
                  const float* __restrict__ bv) {
    const int z = blockIdx.z;
    const float* bias = (z == 0) ? bq : (z == 1) ? bk : bv;
    float* C = (z == 0) ? g_q : (z == 1) ? g_k : g_v;
    gemm_mma_core<true>(g_xh[z], g_xl[z], g_wh[z], g_wl[z], bias, C);
}

__global__ __launch_bounds__(256)
void gemm_out_mma(const float* __restrict__ bo, float* __restrict__ out) {
    gemm_mma_core<false>(g_oh, g_ol, g_wh[3], g_wl[3], bo, out);
}

// ---------------------------------------------------------------------------
// Windowed causal flash attention (fp32), unchanged from R4-passing version.
// ---------------------------------------------------------------------------
#define SMEM_FLOATS (3 * 64 * 65 + 64 * 64)
#define SMEM_BYTES  (SMEM_FLOATS * 4)

__global__ __launch_bounds__(256)
void attn_kernel()
{
    extern __shared__ float sm[];
    float* Qs = sm;                 // [64][65]
    float* Ks = Qs + 64 * 65;       // [64][65]
    float* Sb = Ks + 64 * 65;       // [64][65]
    float* Vs = Sb + 64 * 65;       // [64][64]

    const int tid = threadIdx.x;
    const int tx  = tid & 15;
    const int ty  = tid >> 4;
    const int qb  = blockIdx.x;
    const int h   = blockIdx.y;
    const int b   = blockIdx.z;
    const int q0  = qb * 64;
    const float scale = 0.125f;

    const float* Qg = g_q + (b * HH + h) * SS * DHH;
    const float* Kg = g_k + (b * HH + h) * SS * DHH;
    const float* Vg = g_v + (b * HH + h) * SS * DHH;

#pragma unroll
    for (int p = 0; p < 4; ++p) {
        const int idx = tid + 256 * p;
        const int r = idx >> 4, c = (idx & 15) * 4;
        const float4 v4 = *(const float4*)(Qg + (q0 + r) * DHH + c);
        Qs[r * 65 + c + 0] = v4.x; Qs[r * 65 + c + 1] = v4.y;
        Qs[r * 65 + c + 2] = v4.z; Qs[r * 65 + c + 3] = v4.w;
    }

    float acc[4][4];
    float mrow[4], lrow[4];
#pragma unroll
    for (int i = 0; i < 4; ++i) {
        mrow[i] = -1e30f; lrow[i] = 0.0f;
#pragma unroll
        for (int j = 0; j < 4; ++j) acc[i][j] = 0.0f;
    }

    int kt_lo = qb - 4; if (kt_lo < 0) kt_lo = 0;
    for (int kt = kt_lo; kt <= qb; ++kt) {
        const int k0 = kt * 64;
        __syncthreads();
#pragma unroll
        for (int p = 0; p < 4; ++p) {
            const int idx = tid + 256 * p;
            const int r = idx >> 4, c = (idx & 15) * 4;
            const float4 kv = *(const float4*)(Kg + (k0 + r) * DHH + c);
            Ks[r * 65 + c + 0] = kv.x; Ks[r * 65 + c + 1] = kv.y;
            Ks[r * 65 + c + 2] = kv.z; Ks[r * 65 + c + 3] = kv.w;
            *(float4*)(Vs + r * 64 + c) = *(const float4*)(Vg + (k0 + r) * DHH + c);
        }
        __syncthreads();

        float s[4][4];
#pragma unroll
        for (int i = 0; i < 4; ++i)
#pragma unroll
            for (int j = 0; j < 4; ++j) s[i][j] = 0.0f;

        const float* qrow = Qs + (ty * 4) * 65;
        const float* krow = Ks + (tx * 4) * 65;
#pragma unroll 8
        for (int d = 0; d < 64; ++d) {
            float qv[4], kv[4];
#pragma unroll
            for (int i = 0; i < 4; ++i) qv[i] = qrow[i * 65 + d];
#pragma unroll
            for (int j = 0; j < 4; ++j) kv[j] = krow[j * 65 + d];
#pragma unroll
            for (int i = 0; i < 4; ++i)
#pragma unroll
                for (int j = 0; j < 4; ++j)
                    s[i][j] += qv[i] * kv[j];
        }

        float tmax[4];
#pragma unroll
        for (int i = 0; i < 4; ++i) {
            tmax[i] = -1e30f;
            const int qi = q0 + ty * 4 + i;
#pragma unroll
            for (int j = 0; j < 4; ++j) {
                const int kj = k0 + tx * 4 + j;
                const bool valid = (kj <= qi) && (kj > qi - WIN);
                s[i][j] = valid ? s[i][j] * scale : -1e30f;
                tmax[i] = fmaxf(tmax[i], s[i][j]);
            }
        }
#pragma unroll
        for (int i = 0; i < 4; ++i)
#pragma unroll
            for (int off = 1; off < 16; off <<= 1)
                tmax[i] = fmaxf(tmax[i], __shfl_xor_sync(0xffffffffu, tmax[i], off));

        float tsum[4], corr[4];
#pragma unroll
        for (int i = 0; i < 4; ++i) {
            const float mn = fmaxf(mrow[i], tmax[i]);
            corr[i] = __expf(mrow[i] - mn);
            mrow[i] = mn;
            tsum[i] = 0.0f;
#pragma unroll
            for (int j = 0; j < 4; ++j) {
                const float p = (s[i][j] > -1e29f) ? __expf(s[i][j] - mn) : 0.0f;
                Sb[(ty * 4 + i) * 65 + tx * 4 + j] = p;
                tsum[i] += p;
            }
        }
#pragma unroll
        for (int i = 0; i < 4; ++i)
#pragma unroll
            for (int off = 1; off < 16; off <<= 1)
                tsum[i] += __shfl_xor_sync(0xffffffffu, tsum[i], off);
#pragma unroll
        for (int i = 0; i < 4; ++i) {
            lrow[i] = lrow[i] * corr[i] + tsum[i];
#pragma unroll
            for (int j = 0; j < 4; ++j) acc[i][j] *= corr[i];
        }
        __syncthreads();

#pragma unroll 8
        for (int j = 0; j < 64; ++j) {
            float pv[4], vv[4];
#pragma unroll
            for (int i = 0; i < 4; ++i) pv[i] = Sb[(ty * 4 + i) * 65 + j];
#pragma unroll
            for (int dd = 0; dd < 4; ++dd) vv[dd] = Vs[j * 64 + tx * 4 + dd];
#pragma unroll
            for (int i = 0; i < 4; ++i)
#pragma unroll
                for (int dd = 0; dd < 4; ++dd)
                    acc[i][dd] += pv[i] * vv[dd];
        }
    }

#pragma unroll
    for (int i = 0; i < 4; ++i) {
        const int qi  = q0 + ty * 4 + i;
        const float inv = 1.0f / lrow[i];
        float4 o;
        o.x = acc[i][0] * inv; o.y = acc[i][1] * inv;
        o.z = acc[i][2] * inv; o.w = acc[i][3] * inv;
        *(float4*)(g_attn + (b * SS + qi) * DD + h * DHH + tx * 4) = o;
    }
}

// ---------------------------------------------------------------------------
// Launch
// ---------------------------------------------------------------------------
extern "C" void kernel_launch(void* const* d_in, const int* in_sizes, int n_in,
                              void* d_out, int out_size)
{
    const float* query = (const float*)d_in[0];
    const float* key   = (const float*)d_in[1];
    const float* value = (const float*)d_in[2];
    const float* Wq    = (const float*)d_in[3];
    const float* bq    = (const float*)d_in[4];
    const float* Wk    = (const float*)d_in[5];
    const float* bk    = (const float*)d_in[6];
    const float* Wv    = (const float*)d_in[7];
    const float* bv    = (const float*)d_in[8];
    const float* Wo    = (const float*)d_in[9];
    const float* bo    = (const float*)d_in[10];
    float* out = (float*)d_out;

    // immediate host-side call, capture-safe, idempotent
    cudaFuncSetAttribute(attn_kernel,
                         cudaFuncAttributeMaxDynamicSharedMemorySize, SMEM_BYTES);

    conv_in<<<dim3(MM * DD / 1024, 1, 3), 256>>>(query, key, value);
    conv_w<<<dim3(DD * DD / 1024, 1, 4), 256>>>(Wq, Wk, Wv, Wo);
    gemm_qkv_mma<<<dim3(DD / 128, MM / 128, 3), 256>>>(bq, bk, bv);
    attn_kernel<<<dim3(SS / 64, HH, BB), 256, SMEM_BYTES>>>();
    conv_o<<<dim3(MM * DD / 1024), 256>>>();
    gemm_out_mma<<<dim3(DD / 128, MM / 128, 1), 256>>>(bo, out);
}

// round 11
// speedup vs baseline: 2.1023x; 1.2873x over previous
#include <cuda_runtime.h>
#include <cuda_bf16.h>
#include <cstdint>

// Problem constants
#define BB   2
#define SS   2048
#define DD   1024
#define HH   16
#define DHH  64
#define WIN  256
#define MM   (BB * SS)        // 4096 rows for all GEMMs

// ---------------------------------------------------------------------------
// Scratch (no cudaMalloc allowed) — all bf16 hi/lo pairs
// ---------------------------------------------------------------------------
__device__ __align__(16) __nv_bfloat16 g_xh[3][MM * DD];   // q,k,v inputs
__device__ __align__(16) __nv_bfloat16 g_xl[3][MM * DD];
__device__ __align__(16) __nv_bfloat16 g_wh[4][DD * DD];   // Wq,Wk,Wv,Wo
__device__ __align__(16) __nv_bfloat16 g_wl[4][DD * DD];
__device__ __align__(16) __nv_bfloat16 g_qh[MM * DD];      // [B,H,S,DH]
__device__ __align__(16) __nv_bfloat16 g_ql[MM * DD];
__device__ __align__(16) __nv_bfloat16 g_kh[MM * DD];
__device__ __align__(16) __nv_bfloat16 g_kl[MM * DD];
__device__ __align__(16) __nv_bfloat16 g_vh[MM * DD];
__device__ __align__(16) __nv_bfloat16 g_vl[MM * DD];
__device__ __align__(16) __nv_bfloat16 g_oh[MM * DD];      // attn out [B,S,D]
__device__ __align__(16) __nv_bfloat16 g_ol[MM * DD];

// ---------------------------------------------------------------------------
// PTX helpers (sm_80-era; valid on plain sm_103 target)
// ---------------------------------------------------------------------------
__device__ __forceinline__ uint32_t smem_u32(const void* p) {
    uint32_t a;
    asm("{ .reg .u64 t; cvta.to.shared.u64 t, %1; cvt.u32.u64 %0, t; }"
        : "=r"(a) : "l"(p));
    return a;
}

__device__ __forceinline__ void ldsm4(uint32_t& r0, uint32_t& r1,
                                      uint32_t& r2, uint32_t& r3, uint32_t addr) {
    asm volatile("ldmatrix.sync.aligned.m8n8.x4.shared.b16 {%0,%1,%2,%3}, [%4];"
                 : "=r"(r0), "=r"(r1), "=r"(r2), "=r"(r3) : "r"(addr));
}

__device__ __forceinline__ void ldsm4t(uint32_t& r0, uint32_t& r1,
                                       uint32_t& r2, uint32_t& r3, uint32_t addr) {
    asm volatile("ldmatrix.sync.aligned.m8n8.x4.trans.shared.b16 {%0,%1,%2,%3}, [%4];"
                 : "=r"(r0), "=r"(r1), "=r"(r2), "=r"(r3) : "r"(addr));
}

__device__ __forceinline__ void mma16816(float* c, const uint32_t* a,
                                         uint32_t b0, uint32_t b1) {
    asm volatile(
        "mma.sync.aligned.m16n8k16.row.col.f32.bf16.bf16.f32 "
        "{%0,%1,%2,%3}, {%4,%5,%6,%7}, {%8,%9}, {%0,%1,%2,%3};"
        : "+f"(c[0]), "+f"(c[1]), "+f"(c[2]), "+f"(c[3])
        : "r"(a[0]), "r"(a[1]), "r"(a[2]), "r"(a[3]), "r"(b0), "r"(b1));
}

__device__ __forceinline__ void cp16(uint32_t d, const void* s) {
    asm volatile("cp.async.cg.shared.global [%0], [%1], 16;" :: "r"(d), "l"(s) : "memory");
}
__device__ __forceinline__ void cp_commit() {
    asm volatile("cp.async.commit_group;" ::: "memory");
}
template <int N>
__device__ __forceinline__ void cp_wait() {
    asm volatile("cp.async.wait_group %0;" :: "n"(N) : "memory");
}

__device__ __forceinline__ uint32_t pack_bf16(float x, float y) {
    __nv_bfloat162 t = __floats2bfloat162_rn(x, y);
    return *(uint32_t*)&t;
}
__device__ __forceinline__ void split_pack(float x, float y,
                                           uint32_t& hi, uint32_t& lo) {
    __nv_bfloat16 hx = __float2bfloat16(x), hy = __float2bfloat16(y);
    float lx = x - __bfloat162float(hx);
    float ly = y - __bfloat162float(hy);
    __nv_bfloat162 hp; hp.x = hx; hp.y = hy;
    hi = *(uint32_t*)&hp;
    lo = pack_bf16(lx, ly);
}

// ---------------------------------------------------------------------------
// hi/lo bf16 split conversion kernels (inputs & weights)
// ---------------------------------------------------------------------------
__device__ __forceinline__ void split4(float4 x, uint2& h, uint2& l) {
    uint32_t h0, l0, h1, l1;
    split_pack(x.x, x.y, h0, l0);
    split_pack(x.z, x.w, h1, l1);
    h.x = h0; h.y = h1; l.x = l0; l.y = l1;
}

__global__ __launch_bounds__(256)
void conv_in(const float* __restrict__ q, const float* __restrict__ k,
             const float* __restrict__ v) {
    const int z = blockIdx.z;
    const float* src = (z == 0) ? q : (z == 1) ? k : v;
    const int i = (blockIdx.x * 256 + threadIdx.x) * 4;
    float4 x = *(const float4*)(src + i);
    uint2 h, l;
    split4(x, h, l);
    *(uint2*)(g_xh[z] + i) = h;
    *(uint2*)(g_xl[z] + i) = l;
}

__global__ __launch_bounds__(256)
void conv_w(const float* __restrict__ wq, const float* __restrict__ wk,
            const float* __restrict__ wv, const float* __restrict__ wo) {
    const int z = blockIdx.z;
    const float* src = (z == 0) ? wq : (z == 1) ? wk : (z == 2) ? wv : wo;
    const int i = (blockIdx.x * 256 + threadIdx.x) * 4;
    float4 x = *(const float4*)(src + i);
    uint2 h, l;
    split4(x, h, l);
    *(uint2*)(g_wh[z] + i) = h;
    *(uint2*)(g_wl[z] + i) = l;
}

// ---------------------------------------------------------------------------
// mma.sync GEMM with cp.async 2-stage pipeline.
// C[4096,1024] = A @ W^T + bias. CTA 128x128, 8 warps (4m x 2n), K chunk 32.
// HEAD=true: write bf16 hi/lo head-split [B,H,S,DH]; else fp32 [B,S,D].
// ---------------------------------------------------------------------------
#define ROWB 80                      // padded smem row stride (64B data + 16B)
#define GTILE (128 * ROWB)           // 10240 B per operand tile
#define GBUF  (4 * GTILE)            // 40960 B per stage
#define GEMM_SMEM (2 * GBUF)         // 81920 B

template <bool HEAD>
__device__ __forceinline__ void gemm_mma_core(
    const __nv_bfloat16* __restrict__ Ah, const __nv_bfloat16* __restrict__ Al,
    const __nv_bfloat16* __restrict__ Bh, const __nv_bfloat16* __restrict__ Bl,
    const float* __restrict__ bias,
    __nv_bfloat16* __restrict__ Ch, __nv_bfloat16* __restrict__ Cl,
    float* __restrict__ Cf)
{
    extern __shared__ uint8_t dynsm[];

    const int tid  = threadIdx.x;
    const int lane = tid & 31;
    const int wid  = tid >> 5;
    const int wm   = wid & 3;
    const int wn   = wid >> 2;
    const int m0   = blockIdx.y * 128;
    const int n0   = blockIdx.x * 128;

    const uint8_t* gb[4] = {
        (const uint8_t*)(Ah + m0 * DD), (const uint8_t*)(Al + m0 * DD),
        (const uint8_t*)(Bh + n0 * DD), (const uint8_t*)(Bl + n0 * DD) };

    const uint32_t sbase = smem_u32(dynsm);
    const int rr = tid >> 2;            // row 0..63 (+64 on second it)
    const int gg = (tid & 3) * 16;      // 16B group

    // issue chunk 0
#pragma unroll
    for (int t = 0; t < 4; ++t)
#pragma unroll
        for (int it = 0; it < 2; ++it) {
            const int r = rr + 64 * it;
            cp16(sbase + t * GTILE + r * ROWB + gg, gb[t] + r * 2048 + gg);
        }
    cp_commit();

    float acc[2][8][4];
#pragma unroll
    for (int mi = 0; mi < 2; ++mi)
#pragma unroll
        for (int nj = 0; nj < 8; ++nj)
#pragma unroll
            for (int e = 0; e < 4; ++e) acc[mi][nj][e] = 0.0f;

    const int NT = 32;
    for (int kc = 0; kc < NT; ++kc) {
        const uint32_t cbuf = sbase + (kc & 1) * GBUF;
        if (kc + 1 < NT) {
            const uint32_t nbuf = sbase + ((kc + 1) & 1) * GBUF;
            const int off = (kc + 1) * 64;
#pragma unroll
            for (int t = 0; t < 4; ++t)
#pragma unroll
                for (int it = 0; it < 2; ++it) {
                    const int r = rr + 64 * it;
                    cp16(nbuf + t * GTILE + r * ROWB + gg,
                         gb[t] + r * 2048 + off + gg);
                }
            cp_commit();
            cp_wait<1>();
        } else {
            cp_wait<0>();
        }
        __syncthreads();

#pragma unroll
        for (int ks = 0; ks < 2; ++ks) {
            const uint32_t colb = (uint32_t)(ks * 32 + (lane >> 4) * 16);
            const int      rsel = lane & 15;

            uint32_t ah[2][4], al[2][4];
#pragma unroll
            for (int mi = 0; mi < 2; ++mi) {
                const uint32_t roff = (uint32_t)(wm * 32 + mi * 16 + rsel) * ROWB + colb;
                ldsm4(ah[mi][0], ah[mi][1], ah[mi][2], ah[mi][3], cbuf + 0 * GTILE + roff);
                ldsm4(al[mi][0], al[mi][1], al[mi][2], al[mi][3], cbuf + 1 * GTILE + roff);
            }
            uint32_t bh[4][4], bl[4][4];
#pragma unroll
            for (int nb = 0; nb < 4; ++nb) {
                const uint32_t roff = (uint32_t)(wn * 64 + nb * 16 + rsel) * ROWB + colb;
                ldsm4(bh[nb][0], bh[nb][1], bh[nb][2], bh[nb][3], cbuf + 2 * GTILE + roff);
                ldsm4(bl[nb][0], bl[nb][1], bl[nb][2], bl[nb][3], cbuf + 3 * GTILE + roff);
            }
#pragma unroll
            for (int mi = 0; mi < 2; ++mi)
#pragma unroll
                for (int nb = 0; nb < 4; ++nb)
#pragma unroll
                    for (int hf = 0; hf < 2; ++hf) {
                        float* c = acc[mi][nb * 2 + hf];
                        mma16816(c, ah[mi], bh[nb][hf], bh[nb][2 + hf]);
                        mma16816(c, ah[mi], bl[nb][hf], bl[nb][2 + hf]);
                        mma16816(c, al[mi], bh[nb][hf], bh[nb][2 + hf]);
                    }
        }
        __syncthreads();     // all warps done with cbuf before it is refilled
    }

    // epilogue
#pragma unroll
    for (int mi = 0; mi < 2; ++mi)
#pragma unroll
        for (int nj = 0; nj < 8; ++nj) {
            const int n  = n0 + wn * 64 + nj * 8 + 2 * (lane & 3);
            const float b0 = bias[n], b1 = bias[n + 1];
#pragma unroll
            for (int p = 0; p < 2; ++p) {
                const int m = m0 + wm * 32 + mi * 16 + (lane >> 2) + 8 * p;
                const float ox = acc[mi][nj][2 * p + 0] + b0;
                const float oy = acc[mi][nj][2 * p + 1] + b1;
                if (HEAD) {
                    const int bb = m >> 11;
                    const int s  = m & 2047;
                    const int hh = n >> 6;
                    const int dh = n & 63;
                    const int off = (((bb * HH + hh) * SS + s) * DHH + dh);
                    uint32_t hp, lp;
                    split_pack(ox, oy, hp, lp);
                    *(uint32_t*)(Ch + off) = hp;
                    *(uint32_t*)(Cl + off) = lp;
                } else {
                    float2 o; o.x = ox; o.y = oy;
                    *(float2*)(Cf + m * DD + n) = o;
                }
            }
        }
}

__global__ __launch_bounds__(256)
void gemm_qkv_mma(const float* __restrict__ bq, const float* __restrict__ bk,
                  const float* __restrict__ bv) {
    const int z = blockIdx.z;
    const float* bias = (z == 0) ? bq : (z == 1) ? bk : bv;
    __nv_bfloat16* Ch = (z == 0) ? g_qh : (z == 1) ? g_kh : g_vh;
    __nv_bfloat16* Cl = (z == 0) ? g_ql : (z == 1) ? g_kl : g_vl;
    gemm_mma_core<true>(g_xh[z], g_xl[z], g_wh[z], g_wl[z], bias, Ch, Cl, nullptr);
}

__global__ __launch_bounds__(256)
void gemm_out_mma(const float* __restrict__ bo, float* __restrict__ out) {
    gemm_mma_core<false>(g_oh, g_ol, g_wh[3], g_wl[3], bo, nullptr, nullptr, out);
}

// ---------------------------------------------------------------------------
// Tensor-core windowed causal flash attention.
// Grid (S/64, H, B), 128 threads (4 warps). Warp w owns q rows [16w,16w+16).
// QK^T: 3-pass hi/lo bf16 -> fp32 scores in mma C-frags.
// Softmax in registers (quad shfl). P split hi/lo -> A-frags directly.
// PV: 3-pass with V via ldmatrix.x4.trans. O accum fp32 in C-frags.
// ---------------------------------------------------------------------------
#define STR   144                 // smem row stride (128B data + 16B pad)
#define ATILE (64 * STR)          // 9216 B
#define ATTN_SMEM (6 * ATILE)     // Qh Ql Kh Kl Vh Vl = 55296 B

__global__ __launch_bounds__(128)
void attn_tc()
{
    extern __shared__ uint8_t dynsm[];
    const uint32_t sQh = smem_u32(dynsm);
    const uint32_t sQl = sQh + ATILE;
    const uint32_t sKh = sQh + 2 * ATILE;
    const uint32_t sKl = sQh + 3 * ATILE;
    const uint32_t sVh = sQh + 4 * ATILE;
    const uint32_t sVl = sQh + 5 * ATILE;

    const int tid  = threadIdx.x;
    const int lane = tid & 31;
    const int warp = tid >> 5;
    const int qb   = blockIdx.x;
    const int h    = blockIdx.y;
    const int b    = blockIdx.z;
    const int q0   = qb * 64;
    const float scale = 0.125f;

    const size_t hbase = ((size_t)(b * HH + h)) * SS * DHH;
    const uint8_t* Qgh = (const uint8_t*)(g_qh + hbase + (size_t)q0 * DHH);
    const uint8_t* Qgl = (const uint8_t*)(g_ql + hbase + (size_t)q0 * DHH);

    // load Q tiles (64 rows x 128 B each)
#pragma unroll
    for (int it = 0; it < 4; ++it) {
        const int idx = tid + 128 * it;
        const int r = idx >> 3, c = (idx & 7) * 16;
        *(uint4*)(dynsm + 0 * ATILE + r * STR + c) = *(const uint4*)(Qgh + r * 128 + c);
        *(uint4*)(dynsm + 1 * ATILE + r * STR + c) = *(const uint4*)(Qgl + r * 128 + c);
    }
    __syncthreads();

    // persistent Q A-frags: [pass][kstep][4]
    uint32_t aQ[2][4][4];
#pragma unroll
    for (int s = 0; s < 4; ++s) {
        const uint32_t ro = (uint32_t)(warp * 16 + (lane & 15)) * STR
                          + s * 32 + (lane >> 4) * 16;
        ldsm4(aQ[0][s][0], aQ[0][s][1], aQ[0][s][2], aQ[0][s][3], sQh + ro);
        ldsm4(aQ[1][s][0], aQ[1][s][1], aQ[1][s][2], aQ[1][s][3], sQl + ro);
    }

    const int r0 = q0 + warp * 16 + (lane >> 2);   // global q row (lane row)
    const int r1 = r0 + 8;

    float m0 = -1e30f, m1 = -1e30f, l0 = 0.0f, l1 = 0.0f;
    float oacc[8][4];
#pragma unroll
    for (int nb = 0; nb < 8; ++nb)
#pragma unroll
        for (int e = 0; e < 4; ++e) oacc[nb][e] = 0.0f;

    const int kt_lo = (qb >= 4) ? qb - 4 : 0;
    for (int kt = kt_lo; kt <= qb; ++kt) {
        const int k0 = kt * 64;
        __syncthreads();
        {
            const uint8_t* Kgh = (const uint8_t*)(g_kh + hbase + (size_t)k0 * DHH);
            const uint8_t* Kgl = (const uint8_t*)(g_kl + hbase + (size_t)k0 * DHH);
            const uint8_t* Vgh = (const uint8_t*)(g_vh + hbase + (size_t)k0 * DHH);
            const uint8_t* Vgl = (const uint8_t*)(g_vl + hbase + (size_t)k0 * DHH);
#pragma unroll
            for (int it = 0; it < 4; ++it) {
                const int idx = tid + 128 * it;
                const int r = idx >> 3, c = (idx & 7) * 16;
                *(uint4*)(dynsm + 2 * ATILE + r * STR + c) = *(const uint4*)(Kgh + r * 128 + c);
                *(uint4*)(dynsm + 3 * ATILE + r * STR + c) = *(const uint4*)(Kgl + r * 128 + c);
                *(uint4*)(dynsm + 4 * ATILE + r * STR + c) = *(const uint4*)(Vgh + r * 128 + c);
                *(uint4*)(dynsm + 5 * ATILE + r * STR + c) = *(const uint4*)(Vgl + r * 128 + c);
            }
        }
        __syncthreads();

        // ---- scores: 8 n8-blocks (64 keys) ----
        float sc[8][4];
#pragma unroll
        for (int nb = 0; nb < 8; ++nb)
#pragma unroll
            for (int e = 0; e < 4; ++e) sc[nb][e] = 0.0f;

#pragma unroll
        for (int g = 0; g < 4; ++g) {
#pragma unroll
            for (int s = 0; s < 4; ++s) {
                uint32_t kh[4], kl[4];
                const uint32_t ro = (uint32_t)(g * 16 + (lane & 15)) * STR
                                  + s * 32 + (lane >> 4) * 16;
                ldsm4(kh[0], kh[1], kh[2], kh[3], sKh + ro);
                ldsm4(kl[0], kl[1], kl[2], kl[3], sKl + ro);
                float* c0 = sc[2 * g];
                float* c1 = sc[2 * g + 1];
                mma16816(c0, aQ[0][s], kh[0], kh[2]);
                mma16816(c1, aQ[0][s], kh[1], kh[3]);
                mma16816(c0, aQ[0][s], kl[0], kl[2]);
                mma16816(c1, aQ[0][s], kl[1], kl[3]);
                mma16816(c0, aQ[1][s], kh[0], kh[2]);
                mma16816(c1, aQ[1][s], kh[1], kh[3]);
            }
        }

        // ---- mask + scale + tile row-max ----
        float tm0 = -1e30f, tm1 = -1e30f;
#pragma unroll
        for (int nb = 0; nb < 8; ++nb) {
            const int cb = k0 + nb * 8 + 2 * (lane & 3);
            const bool v0 = (cb     <= r0) && (cb     > r0 - WIN);
            const bool v1 = (cb + 1 <= r0) && (cb + 1 > r0 - WIN);
            const bool v2 = (cb     <= r1) && (cb     > r1 - WIN);
            const bool v3 = (cb + 1 <= r1) && (cb + 1 > r1 - WIN);
            sc[nb][0] = v0 ? sc[nb][0] * scale : -1e30f;
            sc[nb][1] = v1 ? sc[nb][1] * scale : -1e30f;
            sc[nb][2] = v2 ? sc[nb][2] * scale : -1e30f;
            sc[nb][3] = v3 ? sc[nb][3] * scale : -1e30f;
            tm0 = fmaxf(tm0, fmaxf(sc[nb][0], sc[nb][1]));
            tm1 = fmaxf(tm1, fmaxf(sc[nb][2], sc[nb][3]));
        }
        tm0 = fmaxf(tm0, __shfl_xor_sync(0xffffffffu, tm0, 1));
        tm0 = fmaxf(tm0, __shfl_xor_sync(0xffffffffu, tm0, 2));
        tm1 = fmaxf(tm1, __shfl_xor_sync(0xffffffffu, tm1, 1));
        tm1 = fmaxf(tm1, __shfl_xor_sync(0xffffffffu, tm1, 2));

        const float mn0 = fmaxf(m0, tm0), mn1 = fmaxf(m1, tm1);
        const float cr0 = __expf(m0 - mn0), cr1 = __expf(m1 - mn1);
        m0 = mn0; m1 = mn1;

        float ts0 = 0.0f, ts1 = 0.0f;
#pragma unroll
        for (int nb = 0; nb < 8; ++nb) {
            float p0 = (sc[nb][0] > -1e29f) ? __expf(sc[nb][0] - mn0) : 0.0f;
            float p1 = (sc[nb][1] > -1e29f) ? __expf(sc[nb][1] - mn0) : 0.0f;
            float p2 = (sc[nb][2] > -1e29f) ? __expf(sc[nb][2] - mn1) : 0.0f;
            float p3 = (sc[nb][3] > -1e29f) ? __expf(sc[nb][3] - mn1) : 0.0f;
            sc[nb][0] = p0; sc[nb][1] = p1; sc[nb][2] = p2; sc[nb][3] = p3;
            ts0 += p0 + p1; ts1 += p2 + p3;
        }
        ts0 += __shfl_xor_sync(0xffffffffu, ts0, 1);
        ts0 += __shfl_xor_sync(0xffffffffu, ts0, 2);
        ts1 += __shfl_xor_sync(0xffffffffu, ts1, 1);
        ts1 += __shfl_xor_sync(0xffffffffu, ts1, 2);
        l0 = l0 * cr0 + ts0;
        l1 = l1 * cr1 + ts1;
#pragma unroll
        for (int nb = 0; nb < 8; ++nb) {
            oacc[nb][0] *= cr0; oacc[nb][1] *= cr0;
            oacc[nb][2] *= cr1; oacc[nb][3] *= cr1;
        }

        // ---- pack P hi/lo into A-frags: aP[s] over keys [16s,16s+16) ----
        uint32_t aPh[4][4], aPl[4][4];
#pragma unroll
        for (int s = 0; s < 4; ++s) {
            split_pack(sc[2 * s][0],     sc[2 * s][1],     aPh[s][0], aPl[s][0]);
            split_pack(sc[2 * s][2],     sc[2 * s][3],     aPh[s][1], aPl[s][1]);
            split_pack(sc[2 * s + 1][0], sc[2 * s + 1][1], aPh[s][2], aPl[s][2]);
            split_pack(sc[2 * s + 1][2], sc[2 * s + 1][3], aPh[s][3], aPl[s][3]);
        }

        // ---- PV: O[16q x 64dh] += P @ V ----
#pragma unroll
        for (int nb = 0; nb < 8; ++nb) {
#pragma unroll
            for (int kg = 0; kg < 2; ++kg) {
                uint32_t vh[4], vl[4];
                const uint32_t ro = (uint32_t)(kg * 32 + lane) * STR + nb * 16;
                ldsm4t(vh[0], vh[1], vh[2], vh[3], sVh + ro);
                ldsm4t(vl[0], vl[1], vl[2], vl[3], sVl + ro);
                float* o = oacc[nb];
                mma16816(o, aPh[2 * kg],     vh[0], vh[1]);
                mma16816(o, aPh[2 * kg + 1], vh[2], vh[3]);
                mma16816(o, aPh[2 * kg],     vl[0], vl[1]);
                mma16816(o, aPh[2 * kg + 1], vl[2], vl[3]);
                mma16816(o, aPl[2 * kg],     vh[0], vh[1]);
                mma16816(o, aPl[2 * kg + 1], vh[2], vh[3]);
            }
        }
    }

    // ---- epilogue: write bf16 hi/lo attn-out [B,S,D] ----
    const float inv0 = 1.0f / l0;
    const float inv1 = 1.0f / l1;
#pragma unroll
    for (int nb = 0; nb < 8; ++nb) {
        const int dh = nb * 8 + 2 * (lane & 3);
        const size_t o0 = ((size_t)b * SS + r0) * DD + h * DHH + dh;
        const size_t o1 = ((size_t)b * SS + r1) * DD + h * DHH + dh;
        uint32_t hp, lp;
        split_pack(oacc[nb][0] * inv0, oacc[nb][1] * inv0, hp, lp);
        *(uint32_t*)(g_oh + o0) = hp;
        *(uint32_t*)(g_ol + o0) = lp;
        split_pack(oacc[nb][2] * inv1, oacc[nb][3] * inv1, hp, lp);
        *(uint32_t*)(g_oh + o1) = hp;
        *(uint32_t*)(g_ol + o1) = lp;
    }
}

// ---------------------------------------------------------------------------
// Launch
// ---------------------------------------------------------------------------
extern "C" void kernel_launch(void* const* d_in, const int* in_sizes, int n_in,
                              void* d_out, int out_size)
{
    const float* query = (const float*)d_in[0];
    const float* key   = (const float*)d_in[1];
    const float* value = (const float*)d_in[2];
    const float* Wq    = (const float*)d_in[3];
    const float* bq    = (const float*)d_in[4];
    const float* Wk    = (const float*)d_in[5];
    const float* bk    = (const float*)d_in[6];
    const float* Wv    = (const float*)d_in[7];
    const float* bv    = (const float*)d_in[8];
    const float* Wo    = (const float*)d_in[9];
    const float* bo    = (const float*)d_in[10];
    float* out = (float*)d_out;

    // immediate host-side calls, capture-safe, idempotent
    cudaFuncSetAttribute(attn_tc,
                         cudaFuncAttributeMaxDynamicSharedMemorySize, ATTN_SMEM);
    cudaFuncSetAttribute(gemm_qkv_mma,
                         cudaFuncAttributeMaxDynamicSharedMemorySize, GEMM_SMEM);
    cudaFuncSetAttribute(gemm_out_mma,
                         cudaFuncAttributeMaxDynamicSharedMemorySize, GEMM_SMEM);

    conv_in<<<dim3(MM * DD / 1024, 1, 3), 256>>>(query, key, value);
    conv_w<<<dim3(DD * DD / 1024, 1, 4), 256>>>(Wq, Wk, Wv, Wo);
    gemm_qkv_mma<<<dim3(DD / 128, MM / 128, 3), 256, GEMM_SMEM>>>(bq, bk, bv);
    attn_tc<<<dim3(SS / 64, HH, BB), 128, ATTN_SMEM>>>();
    gemm_out_mma<<<dim3(DD / 128, MM / 128, 1), 256, GEMM_SMEM>>>(bo, out);
}

// round 14
// speedup vs baseline: 2.1599x; 1.0274x over previous
#include <cuda_runtime.h>
#include <cuda_bf16.h>
#include <cstdint>

// Problem constants
#define BB   2
#define SS   2048
#define DD   1024
#define HH   16
#define DHH  64
#define WIN  256
#define MM   (BB * SS)        // 4096 rows for all GEMMs

// ---------------------------------------------------------------------------
// Scratch (no cudaMalloc allowed) — all bf16 hi/lo pairs
// ---------------------------------------------------------------------------
__device__ __align__(16) __nv_bfloat16 g_xh[3][MM * DD];   // q,k,v inputs
__device__ __align__(16) __nv_bfloat16 g_xl[3][MM * DD];
__device__ __align__(16) __nv_bfloat16 g_wh[4][DD * DD];   // Wq,Wk,Wv,Wo
__device__ __align__(16) __nv_bfloat16 g_wl[4][DD * DD];
__device__ __align__(16) __nv_bfloat16 g_qh[MM * DD];      // [B,H,S,DH]
__device__ __align__(16) __nv_bfloat16 g_ql[MM * DD];
__device__ __align__(16) __nv_bfloat16 g_kh[MM * DD];
__device__ __align__(16) __nv_bfloat16 g_kl[MM * DD];
__device__ __align__(16) __nv_bfloat16 g_vh[MM * DD];
__device__ __align__(16) __nv_bfloat16 g_vl[MM * DD];
__device__ __align__(16) __nv_bfloat16 g_oh[MM * DD];      // attn out [B,S,D]
__device__ __align__(16) __nv_bfloat16 g_ol[MM * DD];

// ---------------------------------------------------------------------------
// PTX helpers (sm_80-era; valid on plain sm_103 target)
// ---------------------------------------------------------------------------
__device__ __forceinline__ uint32_t smem_u32(const void* p) {
    uint32_t a;
    asm("{ .reg .u64 t; cvta.to.shared.u64 t, %1; cvt.u32.u64 %0, t; }"
        : "=r"(a) : "l"(p));
    return a;
}

__device__ __forceinline__ void ldsm4(uint32_t& r0, uint32_t& r1,
                                      uint32_t& r2, uint32_t& r3, uint32_t addr) {
    asm volatile("ldmatrix.sync.aligned.m8n8.x4.shared.b16 {%0,%1,%2,%3}, [%4];"
                 : "=r"(r0), "=r"(r1), "=r"(r2), "=r"(r3) : "r"(addr));
}

__device__ __forceinline__ void ldsm4t(uint32_t& r0, uint32_t& r1,
                                       uint32_t& r2, uint32_t& r3, uint32_t addr) {
    asm volatile("ldmatrix.sync.aligned.m8n8.x4.trans.shared.b16 {%0,%1,%2,%3}, [%4];"
                 : "=r"(r0), "=r"(r1), "=r"(r2), "=r"(r3) : "r"(addr));
}

__device__ __forceinline__ void mma16816(float* c, const uint32_t* a,
                                         uint32_t b0, uint32_t b1) {
    asm volatile(
        "mma.sync.aligned.m16n8k16.row.col.f32.bf16.bf16.f32 "
        "{%0,%1,%2,%3}, {%4,%5,%6,%7}, {%8,%9}, {%0,%1,%2,%3};"
        : "+f"(c[0]), "+f"(c[1]), "+f"(c[2]), "+f"(c[3])
        : "r"(a[0]), "r"(a[1]), "r"(a[2]), "r"(a[3]), "r"(b0), "r"(b1));
}

__device__ __forceinline__ void cp16(uint32_t d, const void* s) {
    asm volatile("cp.async.cg.shared.global [%0], [%1], 16;" :: "r"(d), "l"(s) : "memory");
}
__device__ __forceinline__ void cp_commit() {
    asm volatile("cp.async.commit_group;" ::: "memory");
}
template <int N>
__device__ __forceinline__ void cp_wait() {
    asm volatile("cp.async.wait_group %0;" :: "n"(N) : "memory");
}

__device__ __forceinline__ uint32_t pack_bf16(float x, float y) {
    __nv_bfloat162 t = __floats2bfloat162_rn(x, y);
    return *(uint32_t*)&t;
}
__device__ __forceinline__ void split_pack(float x, float y,
                                           uint32_t& hi, uint32_t& lo) {
    __nv_bfloat16 hx = __float2bfloat16(x), hy = __float2bfloat16(y);
    float lx = x - __bfloat162float(hx);
    float ly = y - __bfloat162float(hy);
    __nv_bfloat162 hp; hp.x = hx; hp.y = hy;
    hi = *(uint32_t*)&hp;
    lo = pack_bf16(lx, ly);
}

// ---------------------------------------------------------------------------
// hi/lo bf16 split conversion kernels (inputs & weights)
// ---------------------------------------------------------------------------
__device__ __forceinline__ void split4(float4 x, uint2& h, uint2& l) {
    uint32_t h0, l0, h1, l1;
    split_pack(x.x, x.y, h0, l0);
    split_pack(x.z, x.w, h1, l1);
    h.x = h0; h.y = h1; l.x = l0; l.y = l1;
}

__global__ __launch_bounds__(256)
void conv_in(const float* __restrict__ q, const float* __restrict__ k,
             const float* __restrict__ v) {
    const int z = blockIdx.z;
    const float* src = (z == 0) ? q : (z == 1) ? k : v;
    const int i = (blockIdx.x * 256 + threadIdx.x) * 4;
    float4 x = *(const float4*)(src + i);
    uint2 h, l;
    split4(x, h, l);
    *(uint2*)(g_xh[z] + i) = h;
    *(uint2*)(g_xl[z] + i) = l;
}

__global__ __launch_bounds__(256)
void conv_w(const float* __restrict__ wq, const float* __restrict__ wk,
            const float* __restrict__ wv, const float* __restrict__ wo) {
    const int z = blockIdx.z;
    const float* src = (z == 0) ? wq : (z == 1) ? wk : (z == 2) ? wv : wo;
    const int i = (blockIdx.x * 256 + threadIdx.x) * 4;
    float4 x = *(const float4*)(src + i);
    uint2 h, l;
    split4(x, h, l);
    *(uint2*)(g_wh[z] + i) = h;
    *(uint2*)(g_wl[z] + i) = l;
}

// ---------------------------------------------------------------------------
// mma.sync GEMM with cp.async 2-stage pipeline.
// C[4096,1024] = A @ W^T + bias. CTA 128x128, 8 warps (4m x 2n), K chunk 32.
// __launch_bounds__(256,2): reg cap 128 -> 2 CTAs/SM. Inner loop loads B
// frags per n-block (low live set) and runs the 3 hi/lo passes pass-major
// (no back-to-back RAW on the same accumulator).
// HEAD=true: write bf16 hi/lo head-split [B,H,S,DH]; else fp32 [B,S,D].
// ---------------------------------------------------------------------------
#define ROWB 80                      // padded smem row stride (64B data + 16B)
#define GTILE (128 * ROWB)           // 10240 B per operand tile
#define GBUF  (4 * GTILE)            // 40960 B per stage
#define GEMM_SMEM (2 * GBUF)         // 81920 B

template <bool HEAD>
__device__ __forceinline__ void gemm_mma_core(
    const __nv_bfloat16* __restrict__ Ah, const __nv_bfloat16* __restrict__ Al,
    const __nv_bfloat16* __restrict__ Bh, const __nv_bfloat16* __restrict__ Bl,
    const float* __restrict__ bias,
    __nv_bfloat16* __restrict__ Ch, __nv_bfloat16* __restrict__ Cl,
    float* __restrict__ Cf)
{
    extern __shared__ uint8_t dynsm[];

    const int tid  = threadIdx.x;
    const int lane = tid & 31;
    const int wid  = tid >> 5;
    const int wm   = wid & 3;
    const int wn   = wid >> 2;
    const int m0   = blockIdx.y * 128;
    const int n0   = blockIdx.x * 128;

    const uint8_t* gb[4] = {
        (const uint8_t*)(Ah + m0 * DD), (const uint8_t*)(Al + m0 * DD),
        (const uint8_t*)(Bh + n0 * DD), (const uint8_t*)(Bl + n0 * DD) };

    const uint32_t sbase = smem_u32(dynsm);
    const int rr = tid >> 2;            // row 0..63 (+64 on second it)
    const int gg = (tid & 3) * 16;      // 16B group

    // issue chunk 0
#pragma unroll
    for (int t = 0; t < 4; ++t)
#pragma unroll
        for (int it = 0; it < 2; ++it) {
            const int r = rr + 64 * it;
            cp16(sbase + t * GTILE + r * ROWB + gg, gb[t] + r * 2048 + gg);
        }
    cp_commit();

    float acc[2][8][4];
#pragma unroll
    for (int mi = 0; mi < 2; ++mi)
#pragma unroll
        for (int nj = 0; nj < 8; ++nj)
#pragma unroll
            for (int e = 0; e < 4; ++e) acc[mi][nj][e] = 0.0f;

    const int NT = 32;
    for (int kc = 0; kc < NT; ++kc) {
        const uint32_t cbuf = sbase + (kc & 1) * GBUF;
        if (kc + 1 < NT) {
            const uint32_t nbuf = sbase + ((kc + 1) & 1) * GBUF;
            const int off = (kc + 1) * 64;
#pragma unroll
            for (int t = 0; t < 4; ++t)
#pragma unroll
                for (int it = 0; it < 2; ++it) {
                    const int r = rr + 64 * it;
                    cp16(nbuf + t * GTILE + r * ROWB + gg,
                         gb[t] + r * 2048 + off + gg);
                }
            cp_commit();
            cp_wait<1>();
        } else {
            cp_wait<0>();
        }
        __syncthreads();

#pragma unroll
        for (int ks = 0; ks < 2; ++ks) {
            const uint32_t colb = (uint32_t)(ks * 32 + (lane >> 4) * 16);
            const int      rsel = lane & 15;

            uint32_t ah[2][4], al[2][4];
#pragma unroll
            for (int mi = 0; mi < 2; ++mi) {
                const uint32_t roff = (uint32_t)(wm * 32 + mi * 16 + rsel) * ROWB + colb;
                ldsm4(ah[mi][0], ah[mi][1], ah[mi][2], ah[mi][3], cbuf + 0 * GTILE + roff);
                ldsm4(al[mi][0], al[mi][1], al[mi][2], al[mi][3], cbuf + 1 * GTILE + roff);
            }
#pragma unroll
            for (int nb = 0; nb < 4; ++nb) {
                const uint32_t roff = (uint32_t)(wn * 64 + nb * 16 + rsel) * ROWB + colb;
                uint32_t bh[4], bl[4];
                ldsm4(bh[0], bh[1], bh[2], bh[3], cbuf + 2 * GTILE + roff);
                ldsm4(bl[0], bl[1], bl[2], bl[3], cbuf + 3 * GTILE + roff);
                // pass-major: consecutive mmas hit different accumulators
#pragma unroll
                for (int mi = 0; mi < 2; ++mi)
#pragma unroll
                    for (int hf = 0; hf < 2; ++hf)
                        mma16816(acc[mi][nb * 2 + hf], ah[mi], bh[hf], bh[2 + hf]);
#pragma unroll
                for (int mi = 0; mi < 2; ++mi)
#pragma unroll
                    for (int hf = 0; hf < 2; ++hf)
                        mma16816(acc[mi][nb * 2 + hf], ah[mi], bl[hf], bl[2 + hf]);
#pragma unroll
                for (int mi = 0; mi < 2; ++mi)
#pragma unroll
                    for (int hf = 0; hf < 2; ++hf)
                        mma16816(acc[mi][nb * 2 + hf], al[mi], bh[hf], bh[2 + hf]);
            }
        }
        __syncthreads();     // all warps done with cbuf before it is refilled
    }

    // epilogue
#pragma unroll
    for (int mi = 0; mi < 2; ++mi)
#pragma unroll
        for (int nj = 0; nj < 8; ++nj) {
            const int n  = n0 + wn * 64 + nj * 8 + 2 * (lane & 3);
            const float b0 = bias[n], b1 = bias[n + 1];
#pragma unroll
            for (int p = 0; p < 2; ++p) {
                const int m = m0 + wm * 32 + mi * 16 + (lane >> 2) + 8 * p;
                const float ox = acc[mi][nj][2 * p + 0] + b0;
                const float oy = acc[mi][nj][2 * p + 1] + b1;
                if (HEAD) {
                    const int bb = m >> 11;
                    const int s  = m & 2047;
                    const int hh = n >> 6;
                    const int dh = n & 63;
                    const int off = (((bb * HH + hh) * SS + s) * DHH + dh);
                    uint32_t hp, lp;
                    split_pack(ox, oy, hp, lp);
                    *(uint32_t*)(Ch + off) = hp;
                    *(uint32_t*)(Cl + off) = lp;
                } else {
                    float2 o; o.x = ox; o.y = oy;
                    *(float2*)(Cf + m * DD + n) = o;
                }
            }
        }
}

__global__ __launch_bounds__(256, 2)
void gemm_qkv_mma(const float* __restrict__ bq, const float* __restrict__ bk,
                  const float* __restrict__ bv) {
    const int z = blockIdx.z;
    const float* bias = (z == 0) ? bq : (z == 1) ? bk : bv;
    __nv_bfloat16* Ch = (z == 0) ? g_qh : (z == 1) ? g_kh : g_vh;
    __nv_bfloat16* Cl = (z == 0) ? g_ql : (z == 1) ? g_kl : g_vl;
    gemm_mma_core<true>(g_xh[z], g_xl[z], g_wh[z], g_wl[z], bias, Ch, Cl, nullptr);
}

__global__ __launch_bounds__(256, 2)
void gemm_out_mma(const float* __restrict__ bo, float* __restrict__ out) {
    gemm_mma_core<false>(g_oh, g_ol, g_wh[3], g_wl[3], bo, nullptr, nullptr, out);
}

// ---------------------------------------------------------------------------
// Tensor-core windowed causal flash attention.
// Grid (S/64, H, B), 128 threads (4 warps). Warp w owns q rows [16w,16w+16).
// __launch_bounds__(128,4): reg cap 128 -> 4 CTAs/SM (smem 4x55KB fits).
// ---------------------------------------------------------------------------
#define STR   144                 // smem row stride (128B data + 16B pad)
#define ATILE (64 * STR)          // 9216 B
#define ATTN_SMEM (6 * ATILE)     // Qh Ql Kh Kl Vh Vl = 55296 B

__global__ __launch_bounds__(128, 4)
void attn_tc()
{
    extern __shared__ uint8_t dynsm[];
    const uint32_t sQh = smem_u32(dynsm);
    const uint32_t sQl = sQh + ATILE;
    const uint32_t sKh = sQh + 2 * ATILE;
    const uint32_t sKl = sQh + 3 * ATILE;
    const uint32_t sVh = sQh + 4 * ATILE;
    const uint32_t sVl = sQh + 5 * ATILE;

    const int tid  = threadIdx.x;
    const int lane = tid & 31;
    const int warp = tid >> 5;
    const int qb   = blockIdx.x;
    const int h    = blockIdx.y;
    const int b    = blockIdx.z;
    const int q0   = qb * 64;
    const float scale = 0.125f;

    const size_t hbase = ((size_t)(b * HH + h)) * SS * DHH;
    const uint8_t* Qgh = (const uint8_t*)(g_qh + hbase + (size_t)q0 * DHH);
    const uint8_t* Qgl = (const uint8_t*)(g_ql + hbase + (size_t)q0 * DHH);

    // load Q tiles (64 rows x 128 B each)
#pragma unroll
    for (int it = 0; it < 4; ++it) {
        const int idx = tid + 128 * it;
        const int r = idx >> 3, c = (idx & 7) * 16;
        *(uint4*)(dynsm + 0 * ATILE + r * STR + c) = *(const uint4*)(Qgh + r * 128 + c);
        *(uint4*)(dynsm + 1 * ATILE + r * STR + c) = *(const uint4*)(Qgl + r * 128 + c);
    }
    __syncthreads();

    // persistent Q A-frags: [pass][kstep][4]
    uint32_t aQ[2][4][4];
#pragma unroll
    for (int s = 0; s < 4; ++s) {
        const uint32_t ro = (uint32_t)(warp * 16 + (lane & 15)) * STR
                          + s * 32 + (lane >> 4) * 16;
        ldsm4(aQ[0][s][0], aQ[0][s][1], aQ[0][s][2], aQ[0][s][3], sQh + ro);
        ldsm4(aQ[1][s][0], aQ[1][s][1], aQ[1][s][2], aQ[1][s][3], sQl + ro);
    }

    const int r0 = q0 + warp * 16 + (lane >> 2);   // global q row (lane row)
    const int r1 = r0 + 8;

    float m0 = -1e30f, m1 = -1e30f, l0 = 0.0f, l1 = 0.0f;
    float oacc[8][4];
#pragma unroll
    for (int nb = 0; nb < 8; ++nb)
#pragma unroll
        for (int e = 0; e < 4; ++e) oacc[nb][e] = 0.0f;

    const int kt_lo = (qb >= 4) ? qb - 4 : 0;
    for (int kt = kt_lo; kt <= qb; ++kt) {
        const int k0 = kt * 64;
        __syncthreads();
        {
            const uint8_t* Kgh = (const uint8_t*)(g_kh + hbase + (size_t)k0 * DHH);
            const uint8_t* Kgl = (const uint8_t*)(g_kl + hbase + (size_t)k0 * DHH);
            const uint8_t* Vgh = (const uint8_t*)(g_vh + hbase + (size_t)k0 * DHH);
            const uint8_t* Vgl = (const uint8_t*)(g_vl + hbase + (size_t)k0 * DHH);
#pragma unroll
            for (int it = 0; it < 4; ++it) {
                const int idx = tid + 128 * it;
                const int r = idx >> 3, c = (idx & 7) * 16;
                *(uint4*)(dynsm + 2 * ATILE + r * STR + c) = *(const uint4*)(Kgh + r * 128 + c);
                *(uint4*)(dynsm + 3 * ATILE + r * STR + c) = *(const uint4*)(Kgl + r * 128 + c);
                *(uint4*)(dynsm + 4 * ATILE + r * STR + c) = *(const uint4*)(Vgh + r * 128 + c);
                *(uint4*)(dynsm + 5 * ATILE + r * STR + c) = *(const uint4*)(Vgl + r * 128 + c);
            }
        }
        __syncthreads();

        // ---- scores: 8 n8-blocks (64 keys) ----
        float sc[8][4];
#pragma unroll
        for (int nb = 0; nb < 8; ++nb)
#pragma unroll
            for (int e = 0; e < 4; ++e) sc[nb][e] = 0.0f;

#pragma unroll
        for (int g = 0; g < 4; ++g) {
#pragma unroll
            for (int s = 0; s < 4; ++s) {
                uint32_t kh[4], kl[4];
                const uint32_t ro = (uint32_t)(g * 16 + (lane & 15)) * STR
                                  + s * 32 + (lane >> 4) * 16;
                ldsm4(kh[0], kh[1], kh[2], kh[3], sKh + ro);
                ldsm4(kl[0], kl[1], kl[2], kl[3], sKl + ro);
                float* c0 = sc[2 * g];
                float* c1 = sc[2 * g + 1];
                mma16816(c0, aQ[0][s], kh[0], kh[2]);
                mma16816(c1, aQ[0][s], kh[1], kh[3]);
                mma16816(c0, aQ[0][s], kl[0], kl[2]);
                mma16816(c1, aQ[0][s], kl[1], kl[3]);
                mma16816(c0, aQ[1][s], kh[0], kh[2]);
                mma16816(c1, aQ[1][s], kh[1], kh[3]);
            }
        }

        // ---- mask + scale + tile row-max ----
        float tm0 = -1e30f, tm1 = -1e30f;
#pragma unroll
        for (int nb = 0; nb < 8; ++nb) {
            const int cb = k0 + nb * 8 + 2 * (lane & 3);
            const bool v0 = (cb     <= r0) && (cb     > r0 - WIN);
            const bool v1 = (cb + 1 <= r0) && (cb + 1 > r0 - WIN);
            const bool v2 = (cb     <= r1) && (cb     > r1 - WIN);
            const bool v3 = (cb + 1 <= r1) && (cb + 1 > r1 - WIN);
            sc[nb][0] = v0 ? sc[nb][0] * scale : -1e30f;
            sc[nb][1] = v1 ? sc[nb][1] * scale : -1e30f;
            sc[nb][2] = v2 ? sc[nb][2] * scale : -1e30f;
            sc[nb][3] = v3 ? sc[nb][3] * scale : -1e30f;
            tm0 = fmaxf(tm0, fmaxf(sc[nb][0], sc[nb][1]));
            tm1 = fmaxf(tm1, fmaxf(sc[nb][2], sc[nb][3]));
        }
        tm0 = fmaxf(tm0, __shfl_xor_sync(0xffffffffu, tm0, 1));
        tm0 = fmaxf(tm0, __shfl_xor_sync(0xffffffffu, tm0, 2));
        tm1 = fmaxf(tm1, __shfl_xor_sync(0xffffffffu, tm1, 1));
        tm1 = fmaxf(tm1, __shfl_xor_sync(0xffffffffu, tm1, 2));

        const float mn0 = fmaxf(m0, tm0), mn1 = fmaxf(m1, tm1);
        const float cr0 = __expf(m0 - mn0), cr1 = __expf(m1 - mn1);
        m0 = mn0; m1 = mn1;

        float ts0 = 0.0f, ts1 = 0.0f;
#pragma unroll
        for (int nb = 0; nb < 8; ++nb) {
            float p0 = (sc[nb][0] > -1e29f) ? __expf(sc[nb][0] - mn0) : 0.0f;
            float p1 = (sc[nb][1] > -1e29f) ? __expf(sc[nb][1] - mn0) : 0.0f;
            float p2 = (sc[nb][2] > -1e29f) ? __expf(sc[nb][2] - mn1) : 0.0f;
            float p3 = (sc[nb][3] > -1e29f) ? __expf(sc[nb][3] - mn1) : 0.0f;
            sc[nb][0] = p0; sc[nb][1] = p1; sc[nb][2] = p2; sc[nb][3] = p3;
            ts0 += p0 + p1; ts1 += p2 + p3;
        }
        ts0 += __shfl_xor_sync(0xffffffffu, ts0, 1);
        ts0 += __shfl_xor_sync(0xffffffffu, ts0, 2);
        ts1 += __shfl_xor_sync(0xffffffffu, ts1, 1);
        ts1 += __shfl_xor_sync(0xffffffffu, ts1, 2);
        l0 = l0 * cr0 + ts0;
        l1 = l1 * cr1 + ts1;
#pragma unroll
        for (int nb = 0; nb < 8; ++nb) {
            oacc[nb][0] *= cr0; oacc[nb][1] *= cr0;
            oacc[nb][2] *= cr1; oacc[nb][3] *= cr1;
        }

        // ---- pack P hi/lo into A-frags: aP[s] over keys [16s,16s+16) ----
        uint32_t aPh[4][4], aPl[4][4];
#pragma unroll
        for (int s = 0; s < 4; ++s) {
            split_pack(sc[2 * s][0],     sc[2 * s][1],     aPh[s][0], aPl[s][0]);
            split_pack(sc[2 * s][2],     sc[2 * s][3],     aPh[s][1], aPl[s][1]);
            split_pack(sc[2 * s + 1][0], sc[2 * s + 1][1], aPh[s][2], aPl[s][2]);
            split_pack(sc[2 * s + 1][2], sc[2 * s + 1][3], aPh[s][3], aPl[s][3]);
        }

        // ---- PV: O[16q x 64dh] += P @ V ----
#pragma unroll
        for (int nb = 0; nb < 8; ++nb) {
#pragma unroll
            for (int kg = 0; kg < 2; ++kg) {
                uint32_t vh[4], vl[4];
                const uint32_t ro = (uint32_t)(kg * 32 + lane) * STR + nb * 16;
                ldsm4t(vh[0], vh[1], vh[2], vh[3], sVh + ro);
                ldsm4t(vl[0], vl[1], vl[2], vl[3], sVl + ro);
                float* o = oacc[nb];
                mma16816(o, aPh[2 * kg],     vh[0], vh[1]);
                mma16816(o, aPh[2 * kg + 1], vh[2], vh[3]);
                mma16816(o, aPh[2 * kg],     vl[0], vl[1]);
                mma16816(o, aPh[2 * kg + 1], vl[2], vl[3]);
                mma16816(o, aPl[2 * kg],     vh[0], vh[1]);
                mma16816(o, aPl[2 * kg + 1], vh[2], vh[3]);
            }
        }
    }

    // ---- epilogue: write bf16 hi/lo attn-out [B,S,D] ----
    const float inv0 = 1.0f / l0;
    const float inv1 = 1.0f / l1;
#pragma unroll
    for (int nb = 0; nb < 8; ++nb) {
        const int dh = nb * 8 + 2 * (lane & 3);
        const size_t o0 = ((size_t)b * SS + r0) * DD + h * DHH + dh;
        const size_t o1 = ((size_t)b * SS + r1) * DD + h * DHH + dh;
        uint32_t hp, lp;
        split_pack(oacc[nb][0] * inv0, oacc[nb][1] * inv0, hp, lp);
        *(uint32_t*)(g_oh + o0) = hp;
        *(uint32_t*)(g_ol + o0) = lp;
        split_pack(oacc[nb][2] * inv1, oacc[nb][3] * inv1, hp, lp);
        *(uint32_t*)(g_oh + o1) = hp;
        *(uint32_t*)(g_ol + o1) = lp;
    }
}

// ---------------------------------------------------------------------------
// Launch
// ---------------------------------------------------------------------------
extern "C" void kernel_launch(void* const* d_in, const int* in_sizes, int n_in,
                              void* d_out, int out_size)
{
    const float* query = (const float*)d_in[0];
    const float* key   = (const float*)d_in[1];
    const float* value = (const float*)d_in[2];
    const float* Wq    = (const float*)d_in[3];
    const float* bq    = (const float*)d_in[4];
    const float* Wk    = (const float*)d_in[5];
    const float* bk    = (const float*)d_in[6];
    const float* Wv    = (const float*)d_in[7];
    const float* bv    = (const float*)d_in[8];
    const float* Wo    = (const float*)d_in[9];
    const float* bo    = (const float*)d_in[10];
    float* out = (float*)d_out;

    // immediate host-side calls, capture-safe, idempotent
    cudaFuncSetAttribute(attn_tc,
                         cudaFuncAttributeMaxDynamicSharedMemorySize, ATTN_SMEM);
    cudaFuncSetAttribute(gemm_qkv_mma,
                         cudaFuncAttributeMaxDynamicSharedMemorySize, GEMM_SMEM);
    cudaFuncSetAttribute(gemm_out_mma,
                         cudaFuncAttributeMaxDynamicSharedMemorySize, GEMM_SMEM);

    conv_in<<<dim3(MM * DD / 1024, 1, 3), 256>>>(query, key, value);
    conv_w<<<dim3(DD * DD / 1024, 1, 4), 256>>>(Wq, Wk, Wv, Wo);
    gemm_qkv_mma<<<dim3(DD / 128, MM / 128, 3), 256, GEMM_SMEM>>>(bq, bk, bv);
    attn_tc<<<dim3(SS / 64, HH, BB), 128, ATTN_SMEM>>>();
    gemm_out_mma<<<dim3(DD / 128, MM / 128, 1), 256, GEMM_SMEM>>>(bo, out);
}

// round 15
// speedup vs baseline: 2.3747x; 1.0994x over previous
#include <cuda_runtime.h>
#include <cuda_bf16.h>
#include <cstdint>

// Problem constants
#define BB   2
#define SS   2048
#define DD   1024
#define HH   16
#define DHH  64
#define WIN  256
#define MM   (BB * SS)        // 4096 rows for all GEMMs

// ---------------------------------------------------------------------------
// Scratch (no cudaMalloc allowed) — all bf16 hi/lo pairs
// ---------------------------------------------------------------------------
__device__ __align__(16) __nv_bfloat16 g_xh[3][MM * DD];   // q,k,v inputs
__device__ __align__(16) __nv_bfloat16 g_xl[3][MM * DD];
__device__ __align__(16) __nv_bfloat16 g_wh[4][DD * DD];   // Wq,Wk,Wv,Wo
__device__ __align__(16) __nv_bfloat16 g_wl[4][DD * DD];
__device__ __align__(16) __nv_bfloat16 g_qh[MM * DD];      // [B,H,S,DH]
__device__ __align__(16) __nv_bfloat16 g_ql[MM * DD];
__device__ __align__(16) __nv_bfloat16 g_kh[MM * DD];
__device__ __align__(16) __nv_bfloat16 g_kl[MM * DD];
__device__ __align__(16) __nv_bfloat16 g_vh[MM * DD];
__device__ __align__(16) __nv_bfloat16 g_vl[MM * DD];
__device__ __align__(16) __nv_bfloat16 g_oh[MM * DD];      // attn out [B,S,D]
__device__ __align__(16) __nv_bfloat16 g_ol[MM * DD];

// ---------------------------------------------------------------------------
// PTX helpers (sm_80-era; valid on plain sm_103 target)
// ---------------------------------------------------------------------------
__device__ __forceinline__ uint32_t smem_u32(const void* p) {
    uint32_t a;
    asm("{ .reg .u64 t; cvta.to.shared.u64 t, %1; cvt.u32.u64 %0, t; }"
        : "=r"(a) : "l"(p));
    return a;
}

__device__ __forceinline__ void ldsm4(uint32_t& r0, uint32_t& r1,
                                      uint32_t& r2, uint32_t& r3, uint32_t addr) {
    asm volatile("ldmatrix.sync.aligned.m8n8.x4.shared.b16 {%0,%1,%2,%3}, [%4];"
                 : "=r"(r0), "=r"(r1), "=r"(r2), "=r"(r3) : "r"(addr));
}

__device__ __forceinline__ void ldsm4t(uint32_t& r0, uint32_t& r1,
                                       uint32_t& r2, uint32_t& r3, uint32_t addr) {
    asm volatile("ldmatrix.sync.aligned.m8n8.x4.trans.shared.b16 {%0,%1,%2,%3}, [%4];"
                 : "=r"(r0), "=r"(r1), "=r"(r2), "=r"(r3) : "r"(addr));
}

__device__ __forceinline__ void mma16816(float* c, const uint32_t* a,
                                         uint32_t b0, uint32_t b1) {
    asm volatile(
        "mma.sync.aligned.m16n8k16.row.col.f32.bf16.bf16.f32 "
        "{%0,%1,%2,%3}, {%4,%5,%6,%7}, {%8,%9}, {%0,%1,%2,%3};"
        : "+f"(c[0]), "+f"(c[1]), "+f"(c[2]), "+f"(c[3])
        : "r"(a[0]), "r"(a[1]), "r"(a[2]), "r"(a[3]), "r"(b0), "r"(b1));
}

__device__ __forceinline__ void cp16(uint32_t d, const void* s) {
    asm volatile("cp.async.cg.shared.global [%0], [%1], 16;" :: "r"(d), "l"(s) : "memory");
}
__device__ __forceinline__ void cp_commit() {
    asm volatile("cp.async.commit_group;" ::: "memory");
}
template <int N>
__device__ __forceinline__ void cp_wait() {
    asm volatile("cp.async.wait_group %0;" :: "n"(N) : "memory");
}

__device__ __forceinline__ uint32_t pack_bf16(float x, float y) {
    __nv_bfloat162 t = __floats2bfloat162_rn(x, y);
    return *(uint32_t*)&t;
}
__device__ __forceinline__ void split_pack(float x, float y,
                                           uint32_t& hi, uint32_t& lo) {
    __nv_bfloat16 hx = __float2bfloat16(x), hy = __float2bfloat16(y);
    float lx = x - __bfloat162float(hx);
    float ly = y - __bfloat162float(hy);
    __nv_bfloat162 hp; hp.x = hx; hp.y = hy;
    hi = *(uint32_t*)&hp;
    lo = pack_bf16(lx, ly);
}

// XOR swizzles (16B granules), conflict-free ldmatrix phases
#define SWG(r, cg) ((uint32_t)((r) * 64  + ((((cg) ^ (((r) >> 1) & 3))) << 4)))
#define SWA(r, cg) ((uint32_t)((r) * 128 + ((((cg) ^ ((r) & 7))) << 4)))

// ---------------------------------------------------------------------------
// hi/lo bf16 split conversion: one kernel for inputs + weights (flat grid)
// blocks [0,12288): inputs (3 x 4096 blocks); [12288,16384): weights (4 x 1024)
// ---------------------------------------------------------------------------
__device__ __forceinline__ void split4(float4 x, uint2& h, uint2& l) {
    uint32_t h0, l0, h1, l1;
    split_pack(x.x, x.y, h0, l0);
    split_pack(x.z, x.w, h1, l1);
    h.x = h0; h.y = h1; l.x = l0; l.y = l1;
}

__global__ __launch_bounds__(256)
void conv_all(const float* __restrict__ q, const float* __restrict__ k,
              const float* __restrict__ v,
              const float* __restrict__ wq, const float* __restrict__ wk,
              const float* __restrict__ wv, const float* __restrict__ wo)
{
    const int bid = blockIdx.x;
    const float* src;
    __nv_bfloat16 *hi, *lo;
    int i;
    if (bid < 12288) {
        const int z = bid >> 12;
        src = (z == 0) ? q : (z == 1) ? k : v;
        hi = g_xh[z]; lo = g_xl[z];
        i = ((bid & 4095) * 256 + threadIdx.x) * 4;
    } else {
        const int w = bid - 12288;
        const int z = w >> 10;
        src = (z == 0) ? wq : (z == 1) ? wk : (z == 2) ? wv : wo;
        hi = g_wh[z]; lo = g_wl[z];
        i = ((w & 1023) * 256 + threadIdx.x) * 4;
    }
    float4 x = *(const float4*)(src + i);
    uint2 h, l;
    split4(x, h, l);
    *(uint2*)(hi + i) = h;
    *(uint2*)(lo + i) = l;
}

// ---------------------------------------------------------------------------
// mma.sync GEMM, 3-stage cp.async pipeline, XOR swizzle, ONE sync per chunk.
// C[4096,1024] = A @ W^T + bias. CTA 128x128, 8 warps (4m x 2n), K chunk 32.
// ---------------------------------------------------------------------------
#define GTILE (128 * 64)             // 8192 B per operand tile (swizzled)
#define GBUF  (4 * GTILE)            // 32768 B per stage (Ah Al Bh Bl)
#define GEMM_SMEM (3 * GBUF)         // 98304 B

template <bool HEAD>
__device__ __forceinline__ void gemm_mma_core(
    const __nv_bfloat16* __restrict__ Ah, const __nv_bfloat16* __restrict__ Al,
    const __nv_bfloat16* __restrict__ Bh, const __nv_bfloat16* __restrict__ Bl,
    const float* __restrict__ bias,
    __nv_bfloat16* __restrict__ Ch, __nv_bfloat16* __restrict__ Cl,
    float* __restrict__ Cf)
{
    extern __shared__ uint8_t dynsm[];

    const int tid  = threadIdx.x;
    const int lane = tid & 31;
    const int wid  = tid >> 5;
    const int wm   = wid & 3;
    const int wn   = wid >> 2;
    const int m0   = blockIdx.y * 128;
    const int n0   = blockIdx.x * 128;

    const uint8_t* gb[4] = {
        (const uint8_t*)(Ah + m0 * DD), (const uint8_t*)(Al + m0 * DD),
        (const uint8_t*)(Bh + n0 * DD), (const uint8_t*)(Bl + n0 * DD) };

    const uint32_t sbase = smem_u32(dynsm);
    const int rr  = tid >> 2;           // row 0..63 (+64 on second it)
    const int cg0 = tid & 3;            // 16B granule within 64B chunk row

    // preload chunks 0,1 into stages 0,1
#pragma unroll
    for (int s = 0; s < 2; ++s) {
#pragma unroll
        for (int t = 0; t < 4; ++t)
#pragma unroll
            for (int it = 0; it < 2; ++it) {
                const int r = rr + 64 * it;
                cp16(sbase + s * GBUF + t * GTILE + SWG(r, cg0),
                     gb[t] + r * 2048 + s * 64 + cg0 * 16);
            }
        cp_commit();
    }

    float acc[2][8][4];
#pragma unroll
    for (int mi = 0; mi < 2; ++mi)
#pragma unroll
        for (int nj = 0; nj < 8; ++nj)
#pragma unroll
            for (int e = 0; e < 4; ++e) acc[mi][nj][e] = 0.0f;

    const int NT = 32;
    for (int kc = 0; kc < NT; ++kc) {
        if (kc + 1 < NT) cp_wait<1>(); else cp_wait<0>();
        __syncthreads();               // chunk kc visible; all done with kc-1

        if (kc + 2 < NT) {             // prefetch into stage (kc+2)%3 (read at kc-1)
            const uint32_t nbuf = sbase + ((kc + 2) % 3) * GBUF;
            const int off = (kc + 2) * 64;
#pragma unroll
            for (int t = 0; t < 4; ++t)
#pragma unroll
                for (int it = 0; it < 2; ++it) {
                    const int r = rr + 64 * it;
                    cp16(nbuf + t * GTILE + SWG(r, cg0),
                         gb[t] + r * 2048 + off + cg0 * 16);
                }
            cp_commit();
        }

        const uint32_t cbuf = sbase + (kc % 3) * GBUF;
#pragma unroll
        for (int ks = 0; ks < 2; ++ks) {
            const int cg   = ks * 2 + (lane >> 4);
            const int rsel = lane & 15;

            uint32_t ah[2][4], al[2][4];
#pragma unroll
            for (int mi = 0; mi < 2; ++mi) {
                const int row = wm * 32 + mi * 16 + rsel;
                ldsm4(ah[mi][0], ah[mi][1], ah[mi][2], ah[mi][3],
                      cbuf + 0 * GTILE + SWG(row, cg));
                ldsm4(al[mi][0], al[mi][1], al[mi][2], al[mi][3],
                      cbuf + 1 * GTILE + SWG(row, cg));
            }
#pragma unroll
            for (int nb = 0; nb < 4; ++nb) {
                const int row = wn * 64 + nb * 16 + rsel;
                uint32_t bh[4], bl[4];
                ldsm4(bh[0], bh[1], bh[2], bh[3], cbuf + 2 * GTILE + SWG(row, cg));
                ldsm4(bl[0], bl[1], bl[2], bl[3], cbuf + 3 * GTILE + SWG(row, cg));
#pragma unroll
                for (int mi = 0; mi < 2; ++mi)
#pragma unroll
                    for (int hf = 0; hf < 2; ++hf)
                        mma16816(acc[mi][nb * 2 + hf], ah[mi], bh[hf], bh[2 + hf]);
#pragma unroll
                for (int mi = 0; mi < 2; ++mi)
#pragma unroll
                    for (int hf = 0; hf < 2; ++hf)
                        mma16816(acc[mi][nb * 2 + hf], ah[mi], bl[hf], bl[2 + hf]);
#pragma unroll
                for (int mi = 0; mi < 2; ++mi)
#pragma unroll
                    for (int hf = 0; hf < 2; ++hf)
                        mma16816(acc[mi][nb * 2 + hf], al[mi], bh[hf], bh[2 + hf]);
            }
        }
    }

    // epilogue
#pragma unroll
    for (int mi = 0; mi < 2; ++mi)
#pragma unroll
        for (int nj = 0; nj < 8; ++nj) {
            const int n  = n0 + wn * 64 + nj * 8 + 2 * (lane & 3);
            const float b0 = bias[n], b1 = bias[n + 1];
#pragma unroll
            for (int p = 0; p < 2; ++p) {
                const int m = m0 + wm * 32 + mi * 16 + (lane >> 2) + 8 * p;
                const float ox = acc[mi][nj][2 * p + 0] + b0;
                const float oy = acc[mi][nj][2 * p + 1] + b1;
                if (HEAD) {
                    const int bb = m >> 11;
                    const int s  = m & 2047;
                    const int hh = n >> 6;
                    const int dh = n & 63;
                    const int off = (((bb * HH + hh) * SS + s) * DHH + dh);
                    uint32_t hp, lp;
                    split_pack(ox, oy, hp, lp);
                    *(uint32_t*)(Ch + off) = hp;
                    *(uint32_t*)(Cl + off) = lp;
                } else {
                    float2 o; o.x = ox; o.y = oy;
                    *(float2*)(Cf + m * DD + n) = o;
                }
            }
        }
}

__global__ __launch_bounds__(256, 2)
void gemm_qkv_mma(const float* __restrict__ bq, const float* __restrict__ bk,
                  const float* __restrict__ bv) {
    const int z = blockIdx.z;
    const float* bias = (z == 0) ? bq : (z == 1) ? bk : bv;
    __nv_bfloat16* Ch = (z == 0) ? g_qh : (z == 1) ? g_kh : g_vh;
    __nv_bfloat16* Cl = (z == 0) ? g_ql : (z == 1) ? g_kl : g_vl;
    gemm_mma_core<true>(g_xh[z], g_xl[z], g_wh[z], g_wl[z], bias, Ch, Cl, nullptr);
}

__global__ __launch_bounds__(256, 2)
void gemm_out_mma(const float* __restrict__ bo, float* __restrict__ out) {
    gemm_mma_core<false>(g_oh, g_ol, g_wh[3], g_wl[3], bo, nullptr, nullptr, out);
}

// ---------------------------------------------------------------------------
// Tensor-core windowed causal flash attention, 128-row q blocks.
// Grid (S/128, H, B), 256 threads (8 warps). Warp w owns q rows [16w,16w+16).
// K/V double-buffered via cp.async: prefetch tile kt+1 overlaps compute of kt.
// One wait + one sync per tile. 2 CTAs/SM (smem 96 KB, regs capped 128).
// ---------------------------------------------------------------------------
#define QTILE 16384               // 128 rows x 128 B, swizzled
#define KVTILE 8192               // 64 rows x 128 B, swizzled
#define KVSTG (4 * KVTILE)        // Kh Kl Vh Vl = 32768 per stage
#define ATTN_SMEM (2 * QTILE + 2 * KVSTG)   // 98304 B

__global__ __launch_bounds__(256, 2)
void attn_tc()
{
    extern __shared__ uint8_t dynsm[];
    const uint32_t sb  = smem_u32(dynsm);
    const uint32_t sQh = sb;
    const uint32_t sQl = sb + QTILE;
    const uint32_t sKV = sb + 2 * QTILE;       // 2 stages x [Kh Kl Vh Vl]

    const int tid  = threadIdx.x;
    const int lane = tid & 31;
    const int warp = tid >> 5;
    const int qb   = blockIdx.x;
    const int h    = blockIdx.y;
    const int b    = blockIdx.z;
    const int q0   = qb * 128;
    const float scale = 0.125f;

    const size_t hbase = ((size_t)(b * HH + h)) * SS * DHH;
    const uint8_t* Qgh = (const uint8_t*)(g_qh + hbase) + (size_t)q0 * 128;
    const uint8_t* Qgl = (const uint8_t*)(g_ql + hbase) + (size_t)q0 * 128;
    const uint8_t* Kgh = (const uint8_t*)(g_kh + hbase);
    const uint8_t* Kgl = (const uint8_t*)(g_kl + hbase);
    const uint8_t* Vgh = (const uint8_t*)(g_vh + hbase);
    const uint8_t* Vgl = (const uint8_t*)(g_vl + hbase);

    const int tlo = q0 - WIN + 1;
    const int kt_lo = (tlo > 0) ? (tlo >> 6) : 0;
    const int kt_hi = (q0 + 127) >> 6;

    // Q tiles via cp.async (128 rows x 8 granules x 2 tiles)
#pragma unroll
    for (int it = 0; it < 4; ++it) {
        const int idx = tid + 256 * it;
        const int r = idx >> 3, cg = idx & 7;
        cp16(sQh + SWA(r, cg), Qgh + r * 128 + cg * 16);
        cp16(sQl + SWA(r, cg), Qgl + r * 128 + cg * 16);
    }
    cp_commit();

    // first K/V tile into stage 0
    {
        const int k0 = kt_lo * 64;
        const uint32_t st = sKV;
#pragma unroll
        for (int it = 0; it < 2; ++it) {
            const int idx = tid + 256 * it;
            const int r = idx >> 3, cg = idx & 7;
            const size_t go = (size_t)(k0 + r) * 128 + cg * 16;
            const uint32_t so = SWA(r, cg);
            cp16(st + 0 * KVTILE + so, Kgh + go);
            cp16(st + 1 * KVTILE + so, Kgl + go);
            cp16(st + 2 * KVTILE + so, Vgh + go);
            cp16(st + 3 * KVTILE + so, Vgl + go);
        }
        cp_commit();
    }
    cp_wait<0>();
    __syncthreads();

    // persistent Q A-frags: [pass][kstep][4]
    uint32_t aQ[2][4][4];
#pragma unroll
    for (int s = 0; s < 4; ++s) {
        const int row = warp * 16 + (lane & 15);
        const int cg  = s * 2 + (lane >> 4);
        ldsm4(aQ[0][s][0], aQ[0][s][1], aQ[0][s][2], aQ[0][s][3], sQh + SWA(row, cg));
        ldsm4(aQ[1][s][0], aQ[1][s][1], aQ[1][s][2], aQ[1][s][3], sQl + SWA(row, cg));
    }

    const int r0 = q0 + warp * 16 + (lane >> 2);   // global q row (lane row)
    const int r1 = r0 + 8;

    float m0 = -1e30f, m1 = -1e30f, l0 = 0.0f, l1 = 0.0f;
    float oacc[8][4];
#pragma unroll
    for (int nb = 0; nb < 8; ++nb)
#pragma unroll
        for (int e = 0; e < 4; ++e) oacc[nb][e] = 0.0f;

    for (int kt = kt_lo; kt <= kt_hi; ++kt) {
        const int k0 = kt * 64;
        const uint32_t cbuf = sKV + ((kt - kt_lo) & 1) * KVSTG;

        // prefetch next tile (overlaps compute below)
        if (kt < kt_hi) {
            const int nk0 = (kt + 1) * 64;
            const uint32_t nbuf = sKV + ((kt + 1 - kt_lo) & 1) * KVSTG;
#pragma unroll
            for (int it = 0; it < 2; ++it) {
                const int idx = tid + 256 * it;
                const int r = idx >> 3, cg = idx & 7;
                const size_t go = (size_t)(nk0 + r) * 128 + cg * 16;
                const uint32_t so = SWA(r, cg);
                cp16(nbuf + 0 * KVTILE + so, Kgh + go);
                cp16(nbuf + 1 * KVTILE + so, Kgl + go);
                cp16(nbuf + 2 * KVTILE + so, Vgh + go);
                cp16(nbuf + 3 * KVTILE + so, Vgl + go);
            }
            cp_commit();
        }

        const uint32_t cKh = cbuf;
        const uint32_t cKl = cbuf + 1 * KVTILE;
        const uint32_t cVh = cbuf + 2 * KVTILE;
        const uint32_t cVl = cbuf + 3 * KVTILE;

        // ---- scores: 8 n8-blocks (64 keys) ----
        float sc[8][4];
#pragma unroll
        for (int nb = 0; nb < 8; ++nb)
#pragma unroll
            for (int e = 0; e < 4; ++e) sc[nb][e] = 0.0f;

#pragma unroll
        for (int g = 0; g < 4; ++g) {
#pragma unroll
            for (int s = 0; s < 4; ++s) {
                uint32_t kh[4], kl[4];
                const int row = g * 16 + (lane & 15);
                const int cg  = s * 2 + (lane >> 4);
                ldsm4(kh[0], kh[1], kh[2], kh[3], cKh + SWA(row, cg));
                ldsm4(kl[0], kl[1], kl[2], kl[3], cKl + SWA(row, cg));
                float* c0 = sc[2 * g];
                float* c1 = sc[2 * g + 1];
                mma16816(c0, aQ[0][s], kh[0], kh[2]);
                mma16816(c1, aQ[0][s], kh[1], kh[3]);
                mma16816(c0, aQ[0][s], kl[0], kl[2]);
                mma16816(c1, aQ[0][s], kl[1], kl[3]);
                mma16816(c0, aQ[1][s], kh[0], kh[2]);
                mma16816(c1, aQ[1][s], kh[1], kh[3]);
            }
        }

        // ---- mask + scale + tile row-max ----
        float tm0 = -1e30f, tm1 = -1e30f;
#pragma unroll
        for (int nb = 0; nb < 8; ++nb) {
            const int cb = k0 + nb * 8 + 2 * (lane & 3);
            const bool v0 = (cb     <= r0) && (cb     > r0 - WIN);
            const bool v1 = (cb + 1 <= r0) && (cb + 1 > r0 - WIN);
            const bool v2 = (cb     <= r1) && (cb     > r1 - WIN);
            const bool v3 = (cb + 1 <= r1) && (cb + 1 > r1 - WIN);
            sc[nb][0] = v0 ? sc[nb][0] * scale : -1e30f;
            sc[nb][1] = v1 ? sc[nb][1] * scale : -1e30f;
            sc[nb][2] = v2 ? sc[nb][2] * scale : -1e30f;
            sc[nb][3] = v3 ? sc[nb][3] * scale : -1e30f;
            tm0 = fmaxf(tm0, fmaxf(sc[nb][0], sc[nb][1]));
            tm1 = fmaxf(tm1, fmaxf(sc[nb][2], sc[nb][3]));
        }
        tm0 = fmaxf(tm0, __shfl_xor_sync(0xffffffffu, tm0, 1));
        tm0 = fmaxf(tm0, __shfl_xor_sync(0xffffffffu, tm0, 2));
        tm1 = fmaxf(tm1, __shfl_xor_sync(0xffffffffu, tm1, 1));
        tm1 = fmaxf(tm1, __shfl_xor_sync(0xffffffffu, tm1, 2));

        const float mn0 = fmaxf(m0, tm0), mn1 = fmaxf(m1, tm1);
        const float cr0 = __expf(m0 - mn0), cr1 = __expf(m1 - mn1);
        m0 = mn0; m1 = mn1;

        float ts0 = 0.0f, ts1 = 0.0f;
#pragma unroll
        for (int nb = 0; nb < 8; ++nb) {
            float p0 = (sc[nb][0] > -1e29f) ? __expf(sc[nb][0] - mn0) : 0.0f;
            float p1 = (sc[nb][1] > -1e29f) ? __expf(sc[nb][1] - mn0) : 0.0f;
            float p2 = (sc[nb][2] > -1e29f) ? __expf(sc[nb][2] - mn1) : 0.0f;
            float p3 = (sc[nb][3] > -1e29f) ? __expf(sc[nb][3] - mn1) : 0.0f;
            sc[nb][0] = p0; sc[nb][1] = p1; sc[nb][2] = p2; sc[nb][3] = p3;
            ts0 += p0 + p1; ts1 += p2 + p3;
        }
        ts0 += __shfl_xor_sync(0xffffffffu, ts0, 1);
        ts0 += __shfl_xor_sync(0xffffffffu, ts0, 2);
        ts1 += __shfl_xor_sync(0xffffffffu, ts1, 1);
        ts1 += __shfl_xor_sync(0xffffffffu, ts1, 2);
        l0 = l0 * cr0 + ts0;
        l1 = l1 * cr1 + ts1;
#pragma unroll
        for (int nb = 0; nb < 8; ++nb) {
            oacc[nb][0] *= cr0; oacc[nb][1] *= cr0;
            oacc[nb][2] *= cr1; oacc[nb][3] *= cr1;
        }

        // ---- pack P hi/lo into A-frags: aP[s] over keys [16s,16s+16) ----
        uint32_t aPh[4][4], aPl[4][4];
#pragma unroll
        for (int s = 0; s < 4; ++s) {
            split_pack(sc[2 * s][0],     sc[2 * s][1],     aPh[s][0], aPl[s][0]);
            split_pack(sc[2 * s][2],     sc[2 * s][3],     aPh[s][1], aPl[s][1]);
            split_pack(sc[2 * s + 1][0], sc[2 * s + 1][1], aPh[s][2], aPl[s][2]);
            split_pack(sc[2 * s + 1][2], sc[2 * s + 1][3], aPh[s][3], aPl[s][3]);
        }

        // ---- PV: O[16q x 64dh] += P @ V ----
#pragma unroll
        for (int nb = 0; nb < 8; ++nb) {
#pragma unroll
            for (int kg = 0; kg < 2; ++kg) {
                uint32_t vh[4], vl[4];
                const int row = kg * 32 + lane;
                ldsm4t(vh[0], vh[1], vh[2], vh[3], cVh + SWA(row, nb));
                ldsm4t(vl[0], vl[1], vl[2], vl[3], cVl + SWA(row, nb));
                float* o = oacc[nb];
                mma16816(o, aPh[2 * kg],     vh[0], vh[1]);
                mma16816(o, aPh[2 * kg + 1], vh[2], vh[3]);
                mma16816(o, aPh[2 * kg],     vl[0], vl[1]);
                mma16816(o, aPh[2 * kg + 1], vl[2], vl[3]);
                mma16816(o, aPl[2 * kg],     vh[0], vh[1]);
                mma16816(o, aPl[2 * kg + 1], vh[2], vh[3]);
            }
        }

        cp_wait<0>();        // prefetched tile landed
        __syncthreads();     // all warps done with cbuf; nbuf visible
    }

    // ---- epilogue: write bf16 hi/lo attn-out [B,S,D] ----
    const float inv0 = 1.0f / l0;
    const float inv1 = 1.0f / l1;
#pragma unroll
    for (int nb = 0; nb < 8; ++nb) {
        const int dh = nb * 8 + 2 * (lane & 3);
        const size_t o0 = ((size_t)b * SS + r0) * DD + h * DHH + dh;
        const size_t o1 = ((size_t)b * SS + r1) * DD + h * DHH + dh;
        uint32_t hp, lp;
        split_pack(oacc[nb][0] * inv0, oacc[nb][1] * inv0, hp, lp);
        *(uint32_t*)(g_oh + o0) = hp;
        *(uint32_t*)(g_ol + o0) = lp;
        split_pack(oacc[nb][2] * inv1, oacc[nb][3] * inv1, hp, lp);
        *(uint32_t*)(g_oh + o1) = hp;
        *(uint32_t*)(g_ol + o1) = lp;
    }
}

// ---------------------------------------------------------------------------
// Launch
// ---------------------------------------------------------------------------
extern "C" void kernel_launch(void* const* d_in, const int* in_sizes, int n_in,
                              void* d_out, int out_size)
{
    const float* query = (const float*)d_in[0];
    const float* key   = (const float*)d_in[1];
    const float* value = (const float*)d_in[2];
    const float* Wq    = (const float*)d_in[3];
    const float* bq    = (const float*)d_in[4];
    const float* Wk    = (const float*)d_in[5];
    const float* bk    = (const float*)d_in[6];
    const float* Wv    = (const float*)d_in[7];
    const float* bv    = (const float*)d_in[8];
    const float* Wo    = (const float*)d_in[9];
    const float* bo    = (const float*)d_in[10];
    float* out = (float*)d_out;

    // immediate host-side calls, capture-safe, idempotent
    cudaFuncSetAttribute(attn_tc,
                         cudaFuncAttributeMaxDynamicSharedMemorySize, ATTN_SMEM);
    cudaFuncSetAttribute(gemm_qkv_mma,
                         cudaFuncAttributeMaxDynamicSharedMemorySize, GEMM_SMEM);
    cudaFuncSetAttribute(gemm_out_mma,
                         cudaFuncAttributeMaxDynamicSharedMemorySize, GEMM_SMEM);

    conv_all<<<16384, 256>>>(query, key, value, Wq, Wk, Wv, Wo);
    gemm_qkv_mma<<<dim3(DD / 128, MM / 128, 3), 256, GEMM_SMEM>>>(bq, bk, bv);
    attn_tc<<<dim3(SS / 128, HH, BB), 256, ATTN_SMEM>>>();
    gemm_out_mma<<<dim3(DD / 128, MM / 128, 1), 256, GEMM_SMEM>>>(bo, out);
}